// round 8
// baseline (speedup 1.0000x reference)
#include <cuda_runtime.h>
#include <cuda_bf16.h>
#include <cstdint>

#define MAXN 50000
#define MAXE 800000
#define CH 96          // padded feature channels (88 real: 4 x + 84 edge_attr)
#define OC 128
#define OUTC 64
#define EPSV 1e-5f
#define SCAN_CH 2048   // elements per scan CTA

// ---------------- device scratch (static globals: no allocs allowed) -------
__device__ int   g_is64;
__device__ int   g_row[MAXE];
__device__ int   g_col[MAXE];
__device__ int   g_cnt[MAXN];
__device__ int   g_off[MAXN + 1];
__device__ int   g_cur[MAXN];
__device__ int   g_perm[MAXE];
__device__ int   g_blk[64];
__device__ int   g_blkoff[64];
__device__ float g_S[(size_t)MAXN * CH];   // per-node summed features
__device__ float g_M[CH * CH];             // second-moment matrix sum f f^T
__device__ float g_sv[CH];                 // global feature sum s
__device__ float g_mean[OC];
__device__ float g_scale[OC];              // gamma * rsqrt(var+eps)

__device__ __forceinline__ uint32_t smem_u32(const void* p) {
    uint32_t a;
    asm("{ .reg .u64 t; cvta.to.shared.u64 t, %1; cvt.u32.u64 %0, t; }" : "=r"(a) : "l"(p));
    return a;
}

// ---------------- host-side stream/event set (created once, pre-main) ------
struct HxStreams {
    cudaStream_t s1;
    cudaEvent_t evFork, evJoin;
    HxStreams() {
        cudaStreamCreateWithFlags(&s1, cudaStreamNonBlocking);
        cudaEventCreateWithFlags(&evFork, cudaEventDisableTiming);
        cudaEventCreateWithFlags(&evJoin, cudaEventDisableTiming);
    }
};
static HxStreams g_hx;

// ---------------- dtype detection: int64 vs int32 edge_index ----------------
__global__ void k_detect(const void* ei) {
    const long long* p = (const long long*)ei;
    int bad = 0;
    for (int i = threadIdx.x; i < 64; i += 32) {
        long long v = p[i];
        if (v < 0 || v >= MAXN) bad = 1;
    }
    unsigned m = __ballot_sync(0xffffffffu, bad);
    if (threadIdx.x == 0) g_is64 = (m == 0) ? 1 : 0;
}

// ---------------- zero scratch ---------------------------------------------
__global__ void k_zero(int N) {
    int i = blockIdx.x * blockDim.x + threadIdx.x;
    int T = gridDim.x * blockDim.x;
    for (int j = i; j < N; j += T) g_cnt[j] = 0;
    for (int j = i; j < CH * CH; j += T) g_M[j] = 0.f;
    if (i < CH) g_sv[i] = 0.f;
}

// ---------------- convert + histogram fused ---------------------------------
__global__ void k_convhist(const void* ei, int E) {
    int is64 = g_is64;
    int i = blockIdx.x * blockDim.x + threadIdx.x;
    int T = gridDim.x * blockDim.x;
    if (is64) {
        const long long* p = (const long long*)ei;
        for (int e = i; e < E; e += T) {
            int r = (int)p[e];
            g_row[e] = r; g_col[e] = (int)p[E + e];
            atomicAdd(&g_cnt[r], 1);
        }
    } else {
        const int* p = (const int*)ei;
        for (int e = i; e < E; e += T) {
            int r = p[e];
            g_row[e] = r; g_col[e] = p[E + e];
            atomicAdd(&g_cnt[r], 1);
        }
    }
}

// ---------------- multi-CTA exclusive scan ----------------------------------
__global__ void k_scanA(int N) {
    __shared__ int sc[1024];
    int b = blockIdx.x, t = threadIdx.x;
    int i0 = b * SCAN_CH + t * 2;
    int c0 = (i0 < N) ? g_cnt[i0] : 0;
    int c1 = (i0 + 1 < N) ? g_cnt[i0 + 1] : 0;
    int s = c0 + c1;
    sc[t] = s;
    __syncthreads();
#pragma unroll
    for (int d = 1; d < 1024; d <<= 1) {
        int v = (t >= d) ? sc[t - d] : 0;
        __syncthreads();
        sc[t] += v;
        __syncthreads();
    }
    int excl = sc[t] - s;
    if (i0 < N) g_off[i0] = excl;
    if (i0 + 1 < N) g_off[i0 + 1] = excl + c0;
    if (t == 1023) g_blk[b] = sc[1023];
}

__global__ void k_scanB(int nb, int N, int E) {
    int t = threadIdx.x;
    int v = (t < nb) ? g_blk[t] : 0;
    int incl = v;
#pragma unroll
    for (int d = 1; d < 32; d <<= 1) {
        int u = __shfl_up_sync(0xffffffffu, incl, d);
        if (t >= d) incl += u;
    }
    if (t < nb) g_blkoff[t] = incl - v;
    if (t == 0) g_off[N] = E;
}

__global__ void k_scanC(int N) {
    int i = blockIdx.x * blockDim.x + threadIdx.x;
    if (i < N) {
        int v = g_off[i] + g_blkoff[i >> 11];
        g_off[i] = v;
        g_cur[i] = v;
    }
}

__global__ void k_perm(int E) {
    int i = blockIdx.x * blockDim.x + threadIdx.x;
    int T = gridDim.x * blockDim.x;
    for (int e = i; e < E; e += T) {
        int r = g_row[e];
        int p = atomicAdd(&g_cur[r], 1);
        g_perm[p] = e;
    }
}

// ---------------- per-node feature sum: float4 gather, unroll-8 ------------
// lane 0: x[col] (4 ch). lanes 1..21: edge_attr float4 (84 ch). lanes 22,23: pad.
__global__ void k_agg(const float* __restrict__ x, const float* __restrict__ ea,
                      int N) {
    int lane = threadIdx.x & 31;
    int warp = (blockIdx.x * blockDim.x + threadIdx.x) >> 5;
    int nw = (gridDim.x * blockDim.x) >> 5;
    const float4* x4 = (const float4*)x;
    const float4* ea4 = (const float4*)ea;   // 21 float4 per edge row
    for (int n = warp; n < N; n += nw) {
        int beg = g_off[n], end = g_off[n + 1];
        float ax = 0.f, ay = 0.f, az = 0.f, aw = 0.f;
        if (beg < end && lane < 22) {
            int last = end - 1;
            for (int j = beg; j < end; j += 8) {
                int e[8]; float msk[8];
#pragma unroll
                for (int u = 0; u < 8; u++) {
                    int idx = j + u;
                    msk[u] = (idx < end) ? 1.f : 0.f;
                    e[u] = g_perm[(idx < end) ? idx : last];
                }
                float4 v[8];
#pragma unroll
                for (int u = 0; u < 8; u++) {
                    if (lane == 0) v[u] = x4[g_col[e[u]]];
                    else           v[u] = __ldcs(&ea4[(size_t)e[u] * 21 + (lane - 1)]);
                }
#pragma unroll
                for (int u = 0; u < 8; u++) {
                    ax += msk[u] * v[u].x;
                    ay += msk[u] * v[u].y;
                    az += msk[u] * v[u].z;
                    aw += msk[u] * v[u].w;
                }
            }
        }
        if (lane < 24) {
            float4* so4 = (float4*)(g_S + (size_t)n * CH);
            float4 r; r.x = ax; r.y = ay; r.z = az; r.w = aw;
            so4[lane] = r;   // lanes 22,23 write zeros (pad channels 88..95)
        }
    }
}

// ---------------- M = sum_e f f^T via bf16 mma.sync (HMMA) -----------------
#define KB 128
#define ROWB 272
#define TILE_B (CH * ROWB)   // 26112

__device__ __forceinline__ void ldm_x4(uint32_t* r, uint32_t a) {
    asm volatile("ldmatrix.sync.aligned.m8n8.x4.shared.b16 {%0,%1,%2,%3}, [%4];"
                 : "=r"(r[0]), "=r"(r[1]), "=r"(r[2]), "=r"(r[3]) : "r"(a));
}
__device__ __forceinline__ void ldm_x2(uint32_t* r, uint32_t a) {
    asm volatile("ldmatrix.sync.aligned.m8n8.x2.shared.b16 {%0,%1}, [%2];"
                 : "=r"(r[0]), "=r"(r[1]) : "r"(a));
}
__device__ __forceinline__ void mma_bf16(float* c, const uint32_t* a, const uint32_t* b) {
    asm volatile("mma.sync.aligned.m16n8k16.row.col.f32.bf16.bf16.f32 "
                 "{%0,%1,%2,%3}, {%4,%5,%6,%7}, {%8,%9}, {%0,%1,%2,%3};"
                 : "+f"(c[0]), "+f"(c[1]), "+f"(c[2]), "+f"(c[3])
                 : "r"(a[0]), "r"(a[1]), "r"(a[2]), "r"(a[3]), "r"(b[0]), "r"(b[1]));
}

// depends only on k_detect (g_is64) + k_zero (g_M, g_sv): reads ei directly.
__global__ void __launch_bounds__(256, 2)
k_Mmma(const float* __restrict__ x, const void* __restrict__ ei,
       const float* __restrict__ ea, int E) {
    extern __shared__ __align__(16) char dsm[];   // 2 * TILE_B
    int tid = threadIdx.x;
    int lane = tid & 31, w = tid >> 5;
    int warp_m = w >> 2, warp_n = w & 3;   // 2 x 4
    int Rm = warp_m * 48;                  // 3 x 16 rows
    int Rn = warp_n * 24;                  // 3 x 8 cols
    int is64 = g_is64;
    const long long* p64 = (const long long*)ei;
    const int* p32 = (const int*)ei;

    float acc[3][3][4];
#pragma unroll
    for (int i = 0; i < 3; i++)
#pragma unroll
        for (int j = 0; j < 3; j++)
#pragma unroll
            for (int q = 0; q < 4; q++) acc[i][j][q] = 0.f;

    float s0 = 0.f, s1 = 0.f, s2 = 0.f;
    int nchunk = (E + KB - 1) / KB;
    int buf = 0;
    for (int c = blockIdx.x; c < nchunk; c += gridDim.x, buf ^= 1) {
        long long base = (long long)c * KB;
        char* tp = dsm + buf * TILE_B;
#pragma unroll
        for (int half = 0; half < 2; half++) {
            float v0[8], v1[8], v2[8];
#pragma unroll
            for (int u = 0; u < 8; u++) {
                long long e = base + w * 16 + half * 8 + u;
                v0[u] = 0.f; v1[u] = 0.f; v2[u] = 0.f;
                if (e < E) {
                    const float* fe = ea + e * 84;
                    if (lane < 4) {
                        int col = is64 ? (int)p64[E + e] : p32[E + e];
                        v0[u] = x[col * 4 + lane];
                    } else v0[u] = __ldcs(fe + lane - 4);
                    v1[u] = __ldcs(fe + 28 + lane);
                    if (lane < 24) v2[u] = __ldcs(fe + 60 + lane);
                }
            }
#pragma unroll
            for (int u = 0; u < 8; u++) {
                int ee = w * 16 + half * 8 + u;
                s0 += v0[u]; s1 += v1[u]; s2 += v2[u];
                *(__nv_bfloat16*)(tp + lane * ROWB + ee * 2) = __float2bfloat16(v0[u]);
                *(__nv_bfloat16*)(tp + (32 + lane) * ROWB + ee * 2) = __float2bfloat16(v1[u]);
                *(__nv_bfloat16*)(tp + (64 + lane) * ROWB + ee * 2) =
                    (lane < 24) ? __float2bfloat16(v2[u]) : __nv_bfloat16(0.f);
            }
        }
        __syncthreads();
        uint32_t tb = smem_u32(tp);
#pragma unroll
        for (int ks = 0; ks < KB / 16; ks++) {
            uint32_t af[3][4], bf[3][2];
#pragma unroll
            for (int i = 0; i < 3; i++) {
                uint32_t addr = tb + (uint32_t)((Rm + i * 16 + (lane & 15)) * ROWB
                                                + ks * 32 + (lane >> 4) * 16);
                ldm_x4(af[i], addr);
            }
#pragma unroll
            for (int j = 0; j < 3; j++) {
                uint32_t addr = tb + (uint32_t)((Rn + j * 8 + (lane & 7)) * ROWB
                                                + ks * 32 + ((lane >> 3) & 1) * 16);
                ldm_x2(bf[j], addr);
            }
#pragma unroll
            for (int i = 0; i < 3; i++)
#pragma unroll
                for (int j = 0; j < 3; j++) mma_bf16(acc[i][j], af[i], bf[j]);
        }
    }
#pragma unroll
    for (int i = 0; i < 3; i++)
#pragma unroll
        for (int j = 0; j < 3; j++) {
            int row = Rm + i * 16 + (lane >> 2);
            int col = Rn + j * 8 + (lane & 3) * 2;
            atomicAdd(&g_M[row * CH + col], acc[i][j][0]);
            atomicAdd(&g_M[row * CH + col + 1], acc[i][j][1]);
            atomicAdd(&g_M[(row + 8) * CH + col], acc[i][j][2]);
            atomicAdd(&g_M[(row + 8) * CH + col + 1], acc[i][j][3]);
        }
    atomicAdd(&g_sv[lane], s0);
    atomicAdd(&g_sv[32 + lane], s1);
    if (lane < 24) atomicAdd(&g_sv[64 + lane], s2);
}

// ---------------- BN stats --------------------------------------------------
__global__ void k_bn(const float* __restrict__ W1, const float* __restrict__ b1,
                     const float* __restrict__ gamma, float fE) {
    int c = blockIdx.x;
    int t = threadIdx.x;  // 96 threads
    __shared__ float w[CH];
    __shared__ float rq[CH];
    __shared__ float rs[CH];
    w[t] = (t < 88) ? W1[t * OC + c] : 0.f;
    __syncthreads();
    float q = 0.f;
    if (t < 88) {
        const float* Mr = g_M + t * CH;
        for (int k = 0; k < 88; k++) q += Mr[k] * w[k];
        q *= w[t];
    }
    rq[t] = q;
    rs[t] = (t < 88) ? g_sv[t] * w[t] : 0.f;
    __syncthreads();
    if (t == 0) {
        float Q = 0.f, SW = 0.f;
        for (int i = 0; i < 88; i++) { Q += rq[i]; SW += rs[i]; }
        float b = b1[c];
        float mean = SW / fE + b;
        float ex2 = (Q + 2.f * b * SW) / fE + b * b;
        float var = ex2 - mean * mean;
        g_mean[c] = mean;
        g_scale[c] = gamma[c] * rsqrtf(var + EPSV);
    }
}

// ---------------- node output, 4 nodes per warp iteration -------------------
__global__ void k_out(const float* __restrict__ x, const float* __restrict__ W1,
                      const float* __restrict__ b1, const float* __restrict__ beta,
                      const float* __restrict__ W2, const float* __restrict__ b2,
                      float* __restrict__ out, int N) {
    extern __shared__ float sm[];
    float* W1s = sm;             // 88*128
    float* W2s = sm + 88 * OC;   // 132*64
    int tid = threadIdx.x;
    for (int i = tid; i < 88 * OC; i += blockDim.x) W1s[i] = W1[i];
    for (int i = tid; i < 132 * OUTC; i += blockDim.x) W2s[i] = W2[i];
    __syncthreads();
    int lane = tid & 31;
    int warp = (blockIdx.x * blockDim.x + tid) >> 5;
    int nw = (gridDim.x * blockDim.x) >> 5;
    float mn0 = g_mean[lane], mn1 = g_mean[32 + lane], mn2 = g_mean[64 + lane], mn3 = g_mean[96 + lane];
    float sc0 = g_scale[lane], sc1 = g_scale[32 + lane], sc2 = g_scale[64 + lane], sc3 = g_scale[96 + lane];
    float bt0 = beta[lane], bt1 = beta[32 + lane], bt2 = beta[64 + lane], bt3 = beta[96 + lane];
    float bo0 = b1[lane], bo1 = b1[32 + lane], bo2 = b1[64 + lane], bo3 = b1[96 + lane];
    float bb0 = b2[lane], bb1 = b2[32 + lane];

    for (int n0 = warp * 4; n0 < N; n0 += nw * 4) {
        float sr0[4], sr1[4], sr2[4], rcp[4], tv[4];
#pragma unroll
        for (int m = 0; m < 4; m++) {
            int n = n0 + m;
            if (n < N) {
                const float* so = g_S + (size_t)n * CH;
                sr0[m] = so[lane]; sr1[m] = so[32 + lane]; sr2[m] = so[64 + lane];
                int cnt = g_off[n + 1] - g_off[n];
                tv[m] = (cnt > 0) ? 1.f : 0.f;
                rcp[m] = (cnt > 0) ? 1.f / (float)cnt : 0.f;
            } else { sr0[m] = sr1[m] = sr2[m] = 0.f; tv[m] = 0.f; rcp[m] = 0.f; }
        }
        float a0[4] = {0,0,0,0}, a1[4] = {0,0,0,0}, a2[4] = {0,0,0,0}, a3[4] = {0,0,0,0};
#pragma unroll
        for (int cc = 0; cc < 32; cc++) {
            const float* wr = W1s + cc * OC + lane;
            float w0 = wr[0], w1 = wr[32], w2 = wr[64], w3 = wr[96];
#pragma unroll
            for (int m = 0; m < 4; m++) {
                float v = __shfl_sync(0xffffffffu, sr0[m], cc);
                a0[m] += v * w0; a1[m] += v * w1; a2[m] += v * w2; a3[m] += v * w3;
            }
        }
#pragma unroll
        for (int cc = 0; cc < 32; cc++) {
            const float* wr = W1s + (32 + cc) * OC + lane;
            float w0 = wr[0], w1 = wr[32], w2 = wr[64], w3 = wr[96];
#pragma unroll
            for (int m = 0; m < 4; m++) {
                float v = __shfl_sync(0xffffffffu, sr1[m], cc);
                a0[m] += v * w0; a1[m] += v * w1; a2[m] += v * w2; a3[m] += v * w3;
            }
        }
#pragma unroll
        for (int cc = 0; cc < 24; cc++) {
            const float* wr = W1s + (64 + cc) * OC + lane;
            float w0 = wr[0], w1 = wr[32], w2 = wr[64], w3 = wr[96];
#pragma unroll
            for (int m = 0; m < 4; m++) {
                float v = __shfl_sync(0xffffffffu, sr2[m], cc);
                a0[m] += v * w0; a1[m] += v * w1; a2[m] += v * w2; a3[m] += v * w3;
            }
        }
        float ag0[4], ag1[4], ag2[4], ag3[4];
#pragma unroll
        for (int m = 0; m < 4; m++) {
            ag0[m] = ((a0[m] * rcp[m] + bo0 - mn0) * sc0 + bt0) * tv[m];
            ag1[m] = ((a1[m] * rcp[m] + bo1 - mn1) * sc1 + bt1) * tv[m];
            ag2[m] = ((a2[m] * rcp[m] + bo2 - mn2) * sc2 + bt2) * tv[m];
            ag3[m] = ((a3[m] * rcp[m] + bo3 - mn3) * sc3 + bt3) * tv[m];
        }
        float o0[4], o1[4];
#pragma unroll
        for (int m = 0; m < 4; m++) { o0[m] = bb0; o1[m] = bb1; }
#pragma unroll
        for (int k = 0; k < 4; k++) {
            float wa = W2s[k * OUTC + lane], wb = W2s[k * OUTC + 32 + lane];
#pragma unroll
            for (int m = 0; m < 4; m++) {
                int n = n0 + m;
                float xv = (n < N) ? x[(size_t)n * 4 + k] : 0.f;
                o0[m] += xv * wa; o1[m] += xv * wb;
            }
        }
#pragma unroll
        for (int cc = 0; cc < 32; cc++) {
            const float* wr = W2s + (4 + cc) * OUTC + lane;
            float w0 = wr[0], w1 = wr[32];
#pragma unroll
            for (int m = 0; m < 4; m++) {
                float av = __shfl_sync(0xffffffffu, ag0[m], cc);
                o0[m] += av * w0; o1[m] += av * w1;
            }
        }
#pragma unroll
        for (int cc = 0; cc < 32; cc++) {
            const float* wr = W2s + (36 + cc) * OUTC + lane;
            float w0 = wr[0], w1 = wr[32];
#pragma unroll
            for (int m = 0; m < 4; m++) {
                float av = __shfl_sync(0xffffffffu, ag1[m], cc);
                o0[m] += av * w0; o1[m] += av * w1;
            }
        }
#pragma unroll
        for (int cc = 0; cc < 32; cc++) {
            const float* wr = W2s + (68 + cc) * OUTC + lane;
            float w0 = wr[0], w1 = wr[32];
#pragma unroll
            for (int m = 0; m < 4; m++) {
                float av = __shfl_sync(0xffffffffu, ag2[m], cc);
                o0[m] += av * w0; o1[m] += av * w1;
            }
        }
#pragma unroll
        for (int cc = 0; cc < 32; cc++) {
            const float* wr = W2s + (100 + cc) * OUTC + lane;
            float w0 = wr[0], w1 = wr[32];
#pragma unroll
            for (int m = 0; m < 4; m++) {
                float av = __shfl_sync(0xffffffffu, ag3[m], cc);
                o0[m] += av * w0; o1[m] += av * w1;
            }
        }
#pragma unroll
        for (int m = 0; m < 4; m++) {
            int n = n0 + m;
            if (n < N) {
                out[(size_t)n * 64 + lane] = fmaxf(o0[m], 0.f);
                out[(size_t)n * 64 + 32 + lane] = fmaxf(o1[m], 0.f);
            }
        }
    }
}

// ---------------- launcher --------------------------------------------------
extern "C" void kernel_launch(void* const* d_in, const int* in_sizes, int n_in,
                              void* d_out, int out_size) {
    const float* x     = (const float*)d_in[0];
    const void*  ei    = d_in[1];
    const float* ea    = (const float*)d_in[2];
    const float* W1    = (const float*)d_in[3];
    const float* b1    = (const float*)d_in[4];
    const float* gamma = (const float*)d_in[5];
    const float* beta  = (const float*)d_in[6];
    const float* W2    = (const float*)d_in[7];
    const float* b2    = (const float*)d_in[8];
    float* out = (float*)d_out;
    int N = in_sizes[0] / 4;
    int E = in_sizes[2] / 84;
    int nb = (N + SCAN_CH - 1) / SCAN_CH;

    k_detect<<<1, 32>>>(ei);
    k_zero<<<128, 256>>>(N);

    // fork immediately: k_Mmma reads ei directly, needs only g_is64 + zeroed g_M
    cudaEventRecord(g_hx.evFork, 0);
    cudaStreamWaitEvent(g_hx.s1, g_hx.evFork, 0);
    const int msmem = 2 * TILE_B;   // 52224 B
    cudaFuncSetAttribute(k_Mmma, cudaFuncAttributeMaxDynamicSharedMemorySize, msmem);
    k_Mmma<<<296, 256, msmem, g_hx.s1>>>(x, ei, ea, E);
    cudaEventRecord(g_hx.evJoin, g_hx.s1);

    // main chain: convhist -> scan -> perm -> agg
    k_convhist<<<512, 256>>>(ei, E);
    k_scanA<<<nb, 1024>>>(N);
    k_scanB<<<1, 32>>>(nb, N, E);
    k_scanC<<<(N + 255) / 256, 256>>>(N);
    k_perm<<<512, 256>>>(E);
    k_agg<<<1184, 256>>>(x, ea, N);

    // join: bn needs g_M/g_sv from k_Mmma
    cudaStreamWaitEvent(0, g_hx.evJoin, 0);
    k_bn<<<128, 96>>>(W1, b1, gamma, (float)E);
    const int smem = (88 * OC + 132 * OUTC) * 4;  // 78848 B
    cudaFuncSetAttribute(k_out, cudaFuncAttributeMaxDynamicSharedMemorySize, smem);
    k_out<<<296, 256, smem>>>(x, W1, b1, beta, W2, b2, out, N);
}

// round 9
// speedup vs baseline: 1.0297x; 1.0297x over previous
#include <cuda_runtime.h>
#include <cuda_bf16.h>
#include <cstdint>

#define MAXN 50000
#define MAXE 800000
#define CH 96          // padded feature channels (88 real: 4 x + 84 edge_attr)
#define OC 128
#define OUTC 64
#define EPSV 1e-5f
#define SCAN_CH 2048   // elements per scan CTA

// ---------------- device scratch (static globals: no allocs allowed) -------
__device__ int   g_is64;
__device__ int   g_row[MAXE];
__device__ int   g_col[MAXE];
__device__ int   g_cnt[MAXN];
__device__ int   g_off[MAXN + 1];
__device__ int   g_cur[MAXN];
__device__ int   g_perm[MAXE];
__device__ int   g_blk[64];
__device__ int   g_blkoff[64];
__device__ float g_S[(size_t)MAXN * CH];   // per-node summed features
__device__ float g_M[CH * CH];             // second-moment matrix sum f f^T
__device__ float g_sv[CH];                 // global feature sum s
__device__ float g_mean[OC];
__device__ float g_scale[OC];              // gamma * rsqrt(var+eps)

__device__ __forceinline__ uint32_t smem_u32(const void* p) {
    uint32_t a;
    asm("{ .reg .u64 t; cvta.to.shared.u64 t, %1; cvt.u32.u64 %0, t; }" : "=r"(a) : "l"(p));
    return a;
}

// ---------------- host-side stream/event set (created once, pre-main) ------
struct HxStreams {
    cudaStream_t s1;
    cudaEvent_t evFork, evJoin;
    HxStreams() {
        cudaStreamCreateWithFlags(&s1, cudaStreamNonBlocking);
        cudaEventCreateWithFlags(&evFork, cudaEventDisableTiming);
        cudaEventCreateWithFlags(&evJoin, cudaEventDisableTiming);
    }
};
static HxStreams g_hx;

// ---------------- dtype detection: int64 vs int32 edge_index ----------------
__global__ void k_detect(const void* ei) {
    const long long* p = (const long long*)ei;
    int bad = 0;
    for (int i = threadIdx.x; i < 64; i += 32) {
        long long v = p[i];
        if (v < 0 || v >= MAXN) bad = 1;
    }
    unsigned m = __ballot_sync(0xffffffffu, bad);
    if (threadIdx.x == 0) g_is64 = (m == 0) ? 1 : 0;
}

// ---------------- zero scratch ---------------------------------------------
__global__ void k_zero(int N) {
    int i = blockIdx.x * blockDim.x + threadIdx.x;
    int T = gridDim.x * blockDim.x;
    for (int j = i; j < N; j += T) g_cnt[j] = 0;
    for (int j = i; j < CH * CH; j += T) g_M[j] = 0.f;
    if (i < CH) g_sv[i] = 0.f;
}

// ---------------- convert + histogram fused ---------------------------------
__global__ void k_convhist(const void* ei, int E) {
    int is64 = g_is64;
    int i = blockIdx.x * blockDim.x + threadIdx.x;
    int T = gridDim.x * blockDim.x;
    if (is64) {
        const long long* p = (const long long*)ei;
        for (int e = i; e < E; e += T) {
            int r = (int)p[e];
            g_row[e] = r; g_col[e] = (int)p[E + e];
            atomicAdd(&g_cnt[r], 1);
        }
    } else {
        const int* p = (const int*)ei;
        for (int e = i; e < E; e += T) {
            int r = p[e];
            g_row[e] = r; g_col[e] = p[E + e];
            atomicAdd(&g_cnt[r], 1);
        }
    }
}

// ---------------- multi-CTA exclusive scan ----------------------------------
__global__ void k_scanA(int N) {
    __shared__ int sc[1024];
    int b = blockIdx.x, t = threadIdx.x;
    int i0 = b * SCAN_CH + t * 2;
    int c0 = (i0 < N) ? g_cnt[i0] : 0;
    int c1 = (i0 + 1 < N) ? g_cnt[i0 + 1] : 0;
    int s = c0 + c1;
    sc[t] = s;
    __syncthreads();
#pragma unroll
    for (int d = 1; d < 1024; d <<= 1) {
        int v = (t >= d) ? sc[t - d] : 0;
        __syncthreads();
        sc[t] += v;
        __syncthreads();
    }
    int excl = sc[t] - s;
    if (i0 < N) g_off[i0] = excl;
    if (i0 + 1 < N) g_off[i0 + 1] = excl + c0;
    if (t == 1023) g_blk[b] = sc[1023];
}

__global__ void k_scanB(int nb, int N, int E) {
    int t = threadIdx.x;
    int v = (t < nb) ? g_blk[t] : 0;
    int incl = v;
#pragma unroll
    for (int d = 1; d < 32; d <<= 1) {
        int u = __shfl_up_sync(0xffffffffu, incl, d);
        if (t >= d) incl += u;
    }
    if (t < nb) g_blkoff[t] = incl - v;
    if (t == 0) g_off[N] = E;
}

__global__ void k_scanC(int N) {
    int i = blockIdx.x * blockDim.x + threadIdx.x;
    if (i < N) {
        int v = g_off[i] + g_blkoff[i >> 11];
        g_off[i] = v;
        g_cur[i] = v;
    }
}

__global__ void k_perm(int E) {
    int i = blockIdx.x * blockDim.x + threadIdx.x;
    int T = gridDim.x * blockDim.x;
    for (int e = i; e < E; e += T) {
        int r = g_row[e];
        int p = atomicAdd(&g_cur[r], 1);
        g_perm[p] = e;
    }
}

// ---------------- per-node feature sum (gather, predicated unroll-8) -------
// R7-proven scalar form: 3 loads/lane/edge -> 24 outstanding LDGs per batch.
__global__ void k_agg(const float* __restrict__ x, const float* __restrict__ ea,
                      int N) {
    int lane = threadIdx.x & 31;
    int warp = (blockIdx.x * blockDim.x + threadIdx.x) >> 5;
    int nw = (gridDim.x * blockDim.x) >> 5;
    for (int n = warp; n < N; n += nw) {
        int beg = g_off[n], end = g_off[n + 1];
        float a0 = 0.f, a1 = 0.f, a2 = 0.f;
        if (beg < end) {
            int last = end - 1;
            for (int j = beg; j < end; j += 8) {
                int e[8]; float msk[8];
#pragma unroll
                for (int u = 0; u < 8; u++) {
                    int idx = j + u;
                    msk[u] = (idx < end) ? 1.f : 0.f;
                    e[u] = g_perm[(idx < end) ? idx : last];
                }
                float p[8], q[8], r[8];
#pragma unroll
                for (int u = 0; u < 8; u++) {
                    const float* fe = ea + (size_t)e[u] * 84;
                    if (lane < 4) p[u] = x[g_col[e[u]] * 4 + lane];
                    else          p[u] = __ldcs(fe + lane - 4);
                    q[u] = __ldcs(fe + 28 + lane);
                    r[u] = (lane < 24) ? __ldcs(fe + 60 + lane) : 0.f;
                }
#pragma unroll
                for (int u = 0; u < 8; u++) {
                    a0 += msk[u] * p[u];
                    a1 += msk[u] * q[u];
                    a2 += msk[u] * r[u];
                }
            }
        }
        float* so = g_S + (size_t)n * CH;
        so[lane] = a0;
        so[32 + lane] = a1;
        so[64 + lane] = (lane < 24) ? a2 : 0.f;
    }
}

// ---------------- M = sum_e f f^T via bf16 mma.sync (HMMA) -----------------
#define KB 128
#define ROWB 272
#define TILE_B (CH * ROWB)   // 26112

__device__ __forceinline__ void ldm_x4(uint32_t* r, uint32_t a) {
    asm volatile("ldmatrix.sync.aligned.m8n8.x4.shared.b16 {%0,%1,%2,%3}, [%4];"
                 : "=r"(r[0]), "=r"(r[1]), "=r"(r[2]), "=r"(r[3]) : "r"(a));
}
__device__ __forceinline__ void ldm_x2(uint32_t* r, uint32_t a) {
    asm volatile("ldmatrix.sync.aligned.m8n8.x2.shared.b16 {%0,%1}, [%2];"
                 : "=r"(r[0]), "=r"(r[1]) : "r"(a));
}
__device__ __forceinline__ void mma_bf16(float* c, const uint32_t* a, const uint32_t* b) {
    asm volatile("mma.sync.aligned.m16n8k16.row.col.f32.bf16.bf16.f32 "
                 "{%0,%1,%2,%3}, {%4,%5,%6,%7}, {%8,%9}, {%0,%1,%2,%3};"
                 : "+f"(c[0]), "+f"(c[1]), "+f"(c[2]), "+f"(c[3])
                 : "r"(a[0]), "r"(a[1]), "r"(a[2]), "r"(a[3]), "r"(b[0]), "r"(b[1]));
}

// depends only on k_detect (g_is64) + k_zero (g_M, g_sv): reads ei directly.
__global__ void __launch_bounds__(256, 2)
k_Mmma(const float* __restrict__ x, const void* __restrict__ ei,
       const float* __restrict__ ea, int E) {
    extern __shared__ __align__(16) char dsm[];   // 2 * TILE_B
    int tid = threadIdx.x;
    int lane = tid & 31, w = tid >> 5;
    int warp_m = w >> 2, warp_n = w & 3;   // 2 x 4
    int Rm = warp_m * 48;                  // 3 x 16 rows
    int Rn = warp_n * 24;                  // 3 x 8 cols
    int is64 = g_is64;
    const long long* p64 = (const long long*)ei;
    const int* p32 = (const int*)ei;

    float acc[3][3][4];
#pragma unroll
    for (int i = 0; i < 3; i++)
#pragma unroll
        for (int j = 0; j < 3; j++)
#pragma unroll
            for (int q = 0; q < 4; q++) acc[i][j][q] = 0.f;

    float s0 = 0.f, s1 = 0.f, s2 = 0.f;
    int nchunk = (E + KB - 1) / KB;
    int buf = 0;
    for (int c = blockIdx.x; c < nchunk; c += gridDim.x, buf ^= 1) {
        long long base = (long long)c * KB;
        char* tp = dsm + buf * TILE_B;
#pragma unroll
        for (int half = 0; half < 2; half++) {
            float v0[8], v1[8], v2[8];
#pragma unroll
            for (int u = 0; u < 8; u++) {
                long long e = base + w * 16 + half * 8 + u;
                v0[u] = 0.f; v1[u] = 0.f; v2[u] = 0.f;
                if (e < E) {
                    const float* fe = ea + e * 84;
                    if (lane < 4) {
                        int col = is64 ? (int)p64[E + e] : p32[E + e];
                        v0[u] = x[col * 4 + lane];
                    } else v0[u] = __ldcs(fe + lane - 4);
                    v1[u] = __ldcs(fe + 28 + lane);
                    if (lane < 24) v2[u] = __ldcs(fe + 60 + lane);
                }
            }
#pragma unroll
            for (int u = 0; u < 8; u++) {
                int ee = w * 16 + half * 8 + u;
                s0 += v0[u]; s1 += v1[u]; s2 += v2[u];
                *(__nv_bfloat16*)(tp + lane * ROWB + ee * 2) = __float2bfloat16(v0[u]);
                *(__nv_bfloat16*)(tp + (32 + lane) * ROWB + ee * 2) = __float2bfloat16(v1[u]);
                *(__nv_bfloat16*)(tp + (64 + lane) * ROWB + ee * 2) =
                    (lane < 24) ? __float2bfloat16(v2[u]) : __nv_bfloat16(0.f);
            }
        }
        __syncthreads();
        uint32_t tb = smem_u32(tp);
#pragma unroll
        for (int ks = 0; ks < KB / 16; ks++) {
            uint32_t af[3][4], bf[3][2];
#pragma unroll
            for (int i = 0; i < 3; i++) {
                uint32_t addr = tb + (uint32_t)((Rm + i * 16 + (lane & 15)) * ROWB
                                                + ks * 32 + (lane >> 4) * 16);
                ldm_x4(af[i], addr);
            }
#pragma unroll
            for (int j = 0; j < 3; j++) {
                uint32_t addr = tb + (uint32_t)((Rn + j * 8 + (lane & 7)) * ROWB
                                                + ks * 32 + ((lane >> 3) & 1) * 16);
                ldm_x2(bf[j], addr);
            }
#pragma unroll
            for (int i = 0; i < 3; i++)
#pragma unroll
                for (int j = 0; j < 3; j++) mma_bf16(acc[i][j], af[i], bf[j]);
        }
    }
#pragma unroll
    for (int i = 0; i < 3; i++)
#pragma unroll
        for (int j = 0; j < 3; j++) {
            int row = Rm + i * 16 + (lane >> 2);
            int col = Rn + j * 8 + (lane & 3) * 2;
            atomicAdd(&g_M[row * CH + col], acc[i][j][0]);
            atomicAdd(&g_M[row * CH + col + 1], acc[i][j][1]);
            atomicAdd(&g_M[(row + 8) * CH + col], acc[i][j][2]);
            atomicAdd(&g_M[(row + 8) * CH + col + 1], acc[i][j][3]);
        }
    atomicAdd(&g_sv[lane], s0);
    atomicAdd(&g_sv[32 + lane], s1);
    if (lane < 24) atomicAdd(&g_sv[64 + lane], s2);
}

// ---------------- BN stats --------------------------------------------------
__global__ void k_bn(const float* __restrict__ W1, const float* __restrict__ b1,
                     const float* __restrict__ gamma, float fE) {
    int c = blockIdx.x;
    int t = threadIdx.x;  // 96 threads
    __shared__ float w[CH];
    __shared__ float rq[CH];
    __shared__ float rs[CH];
    w[t] = (t < 88) ? W1[t * OC + c] : 0.f;
    __syncthreads();
    float q = 0.f;
    if (t < 88) {
        const float* Mr = g_M + t * CH;
        for (int k = 0; k < 88; k++) q += Mr[k] * w[k];
        q *= w[t];
    }
    rq[t] = q;
    rs[t] = (t < 88) ? g_sv[t] * w[t] : 0.f;
    __syncthreads();
    if (t == 0) {
        float Q = 0.f, SW = 0.f;
        for (int i = 0; i < 88; i++) { Q += rq[i]; SW += rs[i]; }
        float b = b1[c];
        float mean = SW / fE + b;
        float ex2 = (Q + 2.f * b * SW) / fE + b * b;
        float var = ex2 - mean * mean;
        g_mean[c] = mean;
        g_scale[c] = gamma[c] * rsqrtf(var + EPSV);
    }
}

// ---------------- node output, 4 nodes per warp iteration -------------------
__global__ void k_out(const float* __restrict__ x, const float* __restrict__ W1,
                      const float* __restrict__ b1, const float* __restrict__ beta,
                      const float* __restrict__ W2, const float* __restrict__ b2,
                      float* __restrict__ out, int N) {
    extern __shared__ float sm[];
    float* W1s = sm;             // 88*128
    float* W2s = sm + 88 * OC;   // 132*64
    int tid = threadIdx.x;
    for (int i = tid; i < 88 * OC; i += blockDim.x) W1s[i] = W1[i];
    for (int i = tid; i < 132 * OUTC; i += blockDim.x) W2s[i] = W2[i];
    __syncthreads();
    int lane = tid & 31;
    int warp = (blockIdx.x * blockDim.x + tid) >> 5;
    int nw = (gridDim.x * blockDim.x) >> 5;
    float mn0 = g_mean[lane], mn1 = g_mean[32 + lane], mn2 = g_mean[64 + lane], mn3 = g_mean[96 + lane];
    float sc0 = g_scale[lane], sc1 = g_scale[32 + lane], sc2 = g_scale[64 + lane], sc3 = g_scale[96 + lane];
    float bt0 = beta[lane], bt1 = beta[32 + lane], bt2 = beta[64 + lane], bt3 = beta[96 + lane];
    float bo0 = b1[lane], bo1 = b1[32 + lane], bo2 = b1[64 + lane], bo3 = b1[96 + lane];
    float bb0 = b2[lane], bb1 = b2[32 + lane];

    for (int n0 = warp * 4; n0 < N; n0 += nw * 4) {
        float sr0[4], sr1[4], sr2[4], rcp[4], tv[4];
#pragma unroll
        for (int m = 0; m < 4; m++) {
            int n = n0 + m;
            if (n < N) {
                const float* so = g_S + (size_t)n * CH;
                sr0[m] = so[lane]; sr1[m] = so[32 + lane]; sr2[m] = so[64 + lane];
                int cnt = g_off[n + 1] - g_off[n];
                tv[m] = (cnt > 0) ? 1.f : 0.f;
                rcp[m] = (cnt > 0) ? 1.f / (float)cnt : 0.f;
            } else { sr0[m] = sr1[m] = sr2[m] = 0.f; tv[m] = 0.f; rcp[m] = 0.f; }
        }
        float a0[4] = {0,0,0,0}, a1[4] = {0,0,0,0}, a2[4] = {0,0,0,0}, a3[4] = {0,0,0,0};
#pragma unroll
        for (int cc = 0; cc < 32; cc++) {
            const float* wr = W1s + cc * OC + lane;
            float w0 = wr[0], w1 = wr[32], w2 = wr[64], w3 = wr[96];
#pragma unroll
            for (int m = 0; m < 4; m++) {
                float v = __shfl_sync(0xffffffffu, sr0[m], cc);
                a0[m] += v * w0; a1[m] += v * w1; a2[m] += v * w2; a3[m] += v * w3;
            }
        }
#pragma unroll
        for (int cc = 0; cc < 32; cc++) {
            const float* wr = W1s + (32 + cc) * OC + lane;
            float w0 = wr[0], w1 = wr[32], w2 = wr[64], w3 = wr[96];
#pragma unroll
            for (int m = 0; m < 4; m++) {
                float v = __shfl_sync(0xffffffffu, sr1[m], cc);
                a0[m] += v * w0; a1[m] += v * w1; a2[m] += v * w2; a3[m] += v * w3;
            }
        }
#pragma unroll
        for (int cc = 0; cc < 24; cc++) {
            const float* wr = W1s + (64 + cc) * OC + lane;
            float w0 = wr[0], w1 = wr[32], w2 = wr[64], w3 = wr[96];
#pragma unroll
            for (int m = 0; m < 4; m++) {
                float v = __shfl_sync(0xffffffffu, sr2[m], cc);
                a0[m] += v * w0; a1[m] += v * w1; a2[m] += v * w2; a3[m] += v * w3;
            }
        }
        float ag0[4], ag1[4], ag2[4], ag3[4];
#pragma unroll
        for (int m = 0; m < 4; m++) {
            ag0[m] = ((a0[m] * rcp[m] + bo0 - mn0) * sc0 + bt0) * tv[m];
            ag1[m] = ((a1[m] * rcp[m] + bo1 - mn1) * sc1 + bt1) * tv[m];
            ag2[m] = ((a2[m] * rcp[m] + bo2 - mn2) * sc2 + bt2) * tv[m];
            ag3[m] = ((a3[m] * rcp[m] + bo3 - mn3) * sc3 + bt3) * tv[m];
        }
        float o0[4], o1[4];
#pragma unroll
        for (int m = 0; m < 4; m++) { o0[m] = bb0; o1[m] = bb1; }
#pragma unroll
        for (int k = 0; k < 4; k++) {
            float wa = W2s[k * OUTC + lane], wb = W2s[k * OUTC + 32 + lane];
#pragma unroll
            for (int m = 0; m < 4; m++) {
                int n = n0 + m;
                float xv = (n < N) ? x[(size_t)n * 4 + k] : 0.f;
                o0[m] += xv * wa; o1[m] += xv * wb;
            }
        }
#pragma unroll
        for (int cc = 0; cc < 32; cc++) {
            const float* wr = W2s + (4 + cc) * OUTC + lane;
            float w0 = wr[0], w1 = wr[32];
#pragma unroll
            for (int m = 0; m < 4; m++) {
                float av = __shfl_sync(0xffffffffu, ag0[m], cc);
                o0[m] += av * w0; o1[m] += av * w1;
            }
        }
#pragma unroll
        for (int cc = 0; cc < 32; cc++) {
            const float* wr = W2s + (36 + cc) * OUTC + lane;
            float w0 = wr[0], w1 = wr[32];
#pragma unroll
            for (int m = 0; m < 4; m++) {
                float av = __shfl_sync(0xffffffffu, ag1[m], cc);
                o0[m] += av * w0; o1[m] += av * w1;
            }
        }
#pragma unroll
        for (int cc = 0; cc < 32; cc++) {
            const float* wr = W2s + (68 + cc) * OUTC + lane;
            float w0 = wr[0], w1 = wr[32];
#pragma unroll
            for (int m = 0; m < 4; m++) {
                float av = __shfl_sync(0xffffffffu, ag2[m], cc);
                o0[m] += av * w0; o1[m] += av * w1;
            }
        }
#pragma unroll
        for (int cc = 0; cc < 32; cc++) {
            const float* wr = W2s + (100 + cc) * OUTC + lane;
            float w0 = wr[0], w1 = wr[32];
#pragma unroll
            for (int m = 0; m < 4; m++) {
                float av = __shfl_sync(0xffffffffu, ag3[m], cc);
                o0[m] += av * w0; o1[m] += av * w1;
            }
        }
#pragma unroll
        for (int m = 0; m < 4; m++) {
            int n = n0 + m;
            if (n < N) {
                out[(size_t)n * 64 + lane] = fmaxf(o0[m], 0.f);
                out[(size_t)n * 64 + 32 + lane] = fmaxf(o1[m], 0.f);
            }
        }
    }
}

// ---------------- launcher --------------------------------------------------
extern "C" void kernel_launch(void* const* d_in, const int* in_sizes, int n_in,
                              void* d_out, int out_size) {
    const float* x     = (const float*)d_in[0];
    const void*  ei    = d_in[1];
    const float* ea    = (const float*)d_in[2];
    const float* W1    = (const float*)d_in[3];
    const float* b1    = (const float*)d_in[4];
    const float* gamma = (const float*)d_in[5];
    const float* beta  = (const float*)d_in[6];
    const float* W2    = (const float*)d_in[7];
    const float* b2    = (const float*)d_in[8];
    float* out = (float*)d_out;
    int N = in_sizes[0] / 4;
    int E = in_sizes[2] / 84;
    int nb = (N + SCAN_CH - 1) / SCAN_CH;

    k_detect<<<1, 32>>>(ei);
    k_zero<<<128, 256>>>(N);

    // fork immediately: k_Mmma reads ei directly, needs only g_is64 + zeroed g_M
    cudaEventRecord(g_hx.evFork, 0);
    cudaStreamWaitEvent(g_hx.s1, g_hx.evFork, 0);
    const int msmem = 2 * TILE_B;   // 52224 B
    cudaFuncSetAttribute(k_Mmma, cudaFuncAttributeMaxDynamicSharedMemorySize, msmem);
    k_Mmma<<<296, 256, msmem, g_hx.s1>>>(x, ei, ea, E);
    cudaEventRecord(g_hx.evJoin, g_hx.s1);

    // main chain: convhist -> scan -> perm -> agg
    k_convhist<<<512, 256>>>(ei, E);
    k_scanA<<<nb, 1024>>>(N);
    k_scanB<<<1, 32>>>(nb, N, E);
    k_scanC<<<(N + 255) / 256, 256>>>(N);
    k_perm<<<512, 256>>>(E);
    k_agg<<<1184, 256>>>(x, ea, N);

    // join: bn needs g_M/g_sv from k_Mmma
    cudaStreamWaitEvent(0, g_hx.evJoin, 0);
    k_bn<<<128, 96>>>(W1, b1, gamma, (float)E);
    const int smem = (88 * OC + 132 * OUTC) * 4;  // 78848 B
    cudaFuncSetAttribute(k_out, cudaFuncAttributeMaxDynamicSharedMemorySize, smem);
    k_out<<<296, 256, smem>>>(x, W1, b1, beta, W2, b2, out, N);
}

// round 10
// speedup vs baseline: 1.3236x; 1.2854x over previous
#include <cuda_runtime.h>
#include <cuda_bf16.h>
#include <cstdint>

#define MAXN 50000
#define MAXE 800000
#define CH 96          // padded feature channels (88 real: 4 x + 84 edge_attr)
#define OC 128
#define OUTC 64
#define EPSV 1e-5f
#define SCAN_CH 2048   // elements per scan CTA

// ---------------- device scratch (static globals: no allocs allowed) -------
__device__ int   g_is64;
__device__ int   g_row[MAXE];
__device__ int   g_col[MAXE];
__device__ int   g_cnt[MAXN];
__device__ int   g_off[MAXN + 1];
__device__ int   g_cur[MAXN];
__device__ int   g_perm[MAXE];
__device__ int   g_blk[64];
__device__ int   g_blkoff[64];
__device__ float g_S[(size_t)MAXN * CH];   // per-node summed features
__device__ float g_M[CH * CH];             // second-moment matrix sum f f^T
__device__ float g_sv[CH];                 // global feature sum s
__device__ float g_mean[OC];
__device__ float g_scale[OC];              // gamma * rsqrt(var+eps)

__device__ __forceinline__ uint32_t smem_u32(const void* p) {
    uint32_t a;
    asm("{ .reg .u64 t; cvta.to.shared.u64 t, %1; cvt.u32.u64 %0, t; }" : "=r"(a) : "l"(p));
    return a;
}

// ---------------- host-side stream/event set (created once, pre-main) ------
struct HxStreams {
    cudaStream_t s1;
    cudaEvent_t evFork, evJoin;
    HxStreams() {
        cudaStreamCreateWithFlags(&s1, cudaStreamNonBlocking);
        cudaEventCreateWithFlags(&evFork, cudaEventDisableTiming);
        cudaEventCreateWithFlags(&evJoin, cudaEventDisableTiming);
    }
};
static HxStreams g_hx;

// ---------------- dtype detection: int64 vs int32 edge_index ----------------
__global__ void k_detect(const void* ei) {
    const long long* p = (const long long*)ei;
    int bad = 0;
    for (int i = threadIdx.x; i < 64; i += 32) {
        long long v = p[i];
        if (v < 0 || v >= MAXN) bad = 1;
    }
    unsigned m = __ballot_sync(0xffffffffu, bad);
    if (threadIdx.x == 0) g_is64 = (m == 0) ? 1 : 0;
}

// ---------------- zero scratch ---------------------------------------------
__global__ void k_zero(int N) {
    int i = blockIdx.x * blockDim.x + threadIdx.x;
    int T = gridDim.x * blockDim.x;
    for (int j = i; j < N; j += T) g_cnt[j] = 0;
    for (int j = i; j < CH * CH; j += T) g_M[j] = 0.f;
    if (i < CH) g_sv[i] = 0.f;
}

// ---------------- convert + histogram fused ---------------------------------
__global__ void k_convhist(const void* ei, int E) {
    int is64 = g_is64;
    int i = blockIdx.x * blockDim.x + threadIdx.x;
    int T = gridDim.x * blockDim.x;
    if (is64) {
        const long long* p = (const long long*)ei;
        for (int e = i; e < E; e += T) {
            int r = (int)p[e];
            g_row[e] = r; g_col[e] = (int)p[E + e];
            atomicAdd(&g_cnt[r], 1);
        }
    } else {
        const int* p = (const int*)ei;
        for (int e = i; e < E; e += T) {
            int r = p[e];
            g_row[e] = r; g_col[e] = p[E + e];
            atomicAdd(&g_cnt[r], 1);
        }
    }
}

// ---------------- multi-CTA exclusive scan ----------------------------------
__global__ void k_scanA(int N) {
    __shared__ int sc[1024];
    int b = blockIdx.x, t = threadIdx.x;
    int i0 = b * SCAN_CH + t * 2;
    int c0 = (i0 < N) ? g_cnt[i0] : 0;
    int c1 = (i0 + 1 < N) ? g_cnt[i0 + 1] : 0;
    int s = c0 + c1;
    sc[t] = s;
    __syncthreads();
#pragma unroll
    for (int d = 1; d < 1024; d <<= 1) {
        int v = (t >= d) ? sc[t - d] : 0;
        __syncthreads();
        sc[t] += v;
        __syncthreads();
    }
    int excl = sc[t] - s;
    if (i0 < N) g_off[i0] = excl;
    if (i0 + 1 < N) g_off[i0 + 1] = excl + c0;
    if (t == 1023) g_blk[b] = sc[1023];
}

__global__ void k_scanB(int nb, int N, int E) {
    int t = threadIdx.x;
    int v = (t < nb) ? g_blk[t] : 0;
    int incl = v;
#pragma unroll
    for (int d = 1; d < 32; d <<= 1) {
        int u = __shfl_up_sync(0xffffffffu, incl, d);
        if (t >= d) incl += u;
    }
    if (t < nb) g_blkoff[t] = incl - v;
    if (t == 0) g_off[N] = E;
}

__global__ void k_scanC(int N) {
    int i = blockIdx.x * blockDim.x + threadIdx.x;
    if (i < N) {
        int v = g_off[i] + g_blkoff[i >> 11];
        g_off[i] = v;
        g_cur[i] = v;
    }
}

__global__ void k_perm(int E) {
    int i = blockIdx.x * blockDim.x + threadIdx.x;
    int T = gridDim.x * blockDim.x;
    for (int e = i; e < E; e += T) {
        int r = g_row[e];
        int p = atomicAdd(&g_cur[r], 1);
        g_perm[p] = e;
    }
}

// ---------------- per-node feature sum (gather, predicated unroll-8) -------
// R7-proven scalar form: 3 loads/lane/edge -> 24 outstanding LDGs per batch.
__global__ void k_agg(const float* __restrict__ x, const float* __restrict__ ea,
                      int N) {
    int lane = threadIdx.x & 31;
    int warp = (blockIdx.x * blockDim.x + threadIdx.x) >> 5;
    int nw = (gridDim.x * blockDim.x) >> 5;
    for (int n = warp; n < N; n += nw) {
        int beg = g_off[n], end = g_off[n + 1];
        float a0 = 0.f, a1 = 0.f, a2 = 0.f;
        if (beg < end) {
            int last = end - 1;
            for (int j = beg; j < end; j += 8) {
                int e[8]; float msk[8];
#pragma unroll
                for (int u = 0; u < 8; u++) {
                    int idx = j + u;
                    msk[u] = (idx < end) ? 1.f : 0.f;
                    e[u] = g_perm[(idx < end) ? idx : last];
                }
                float p[8], q[8], r[8];
#pragma unroll
                for (int u = 0; u < 8; u++) {
                    const float* fe = ea + (size_t)e[u] * 84;
                    if (lane < 4) p[u] = x[g_col[e[u]] * 4 + lane];
                    else          p[u] = __ldcs(fe + lane - 4);
                    q[u] = __ldcs(fe + 28 + lane);
                    r[u] = (lane < 24) ? __ldcs(fe + 60 + lane) : 0.f;
                }
#pragma unroll
                for (int u = 0; u < 8; u++) {
                    a0 += msk[u] * p[u];
                    a1 += msk[u] * q[u];
                    a2 += msk[u] * r[u];
                }
            }
        }
        float* so = g_S + (size_t)n * CH;
        so[lane] = a0;
        so[32 + lane] = a1;
        so[64 + lane] = (lane < 24) ? a2 : 0.f;
    }
}

// ---------------- M = sum_e f f^T via bf16 mma.sync (HMMA) -----------------
// Double-buffered 96x128 bf16 tiles (row stride 272B, conflict-free ldmatrix).
// Warps 2x4: warp covers 48 rows x 24 cols as 3x3 m16n8k16 tiles.
// bf16x2-packed smem stores: consecutive edges share one 4-byte STS.
#define KB 128
#define ROWB 272
#define TILE_B (CH * ROWB)   // 26112

__device__ __forceinline__ void ldm_x4(uint32_t* r, uint32_t a) {
    asm volatile("ldmatrix.sync.aligned.m8n8.x4.shared.b16 {%0,%1,%2,%3}, [%4];"
                 : "=r"(r[0]), "=r"(r[1]), "=r"(r[2]), "=r"(r[3]) : "r"(a));
}
__device__ __forceinline__ void ldm_x2(uint32_t* r, uint32_t a) {
    asm volatile("ldmatrix.sync.aligned.m8n8.x2.shared.b16 {%0,%1}, [%2];"
                 : "=r"(r[0]), "=r"(r[1]) : "r"(a));
}
__device__ __forceinline__ void mma_bf16(float* c, const uint32_t* a, const uint32_t* b) {
    asm volatile("mma.sync.aligned.m16n8k16.row.col.f32.bf16.bf16.f32 "
                 "{%0,%1,%2,%3}, {%4,%5,%6,%7}, {%8,%9}, {%0,%1,%2,%3};"
                 : "+f"(c[0]), "+f"(c[1]), "+f"(c[2]), "+f"(c[3])
                 : "r"(a[0]), "r"(a[1]), "r"(a[2]), "r"(a[3]), "r"(b[0]), "r"(b[1]));
}

__global__ void __launch_bounds__(256, 2)
k_Mmma(const float* __restrict__ x, const float* __restrict__ ea, int E) {
    extern __shared__ __align__(16) char dsm[];   // 2 * TILE_B
    int tid = threadIdx.x;
    int lane = tid & 31, w = tid >> 5;
    int warp_m = w >> 2, warp_n = w & 3;   // 2 x 4
    int Rm = warp_m * 48;                  // 3 x 16 rows
    int Rn = warp_n * 24;                  // 3 x 8 cols

    float acc[3][3][4];
#pragma unroll
    for (int i = 0; i < 3; i++)
#pragma unroll
        for (int j = 0; j < 3; j++)
#pragma unroll
            for (int q = 0; q < 4; q++) acc[i][j][q] = 0.f;

    float s0 = 0.f, s1 = 0.f, s2 = 0.f;
    int nchunk = (E + KB - 1) / KB;
    int buf = 0;
    for (int c = blockIdx.x; c < nchunk; c += gridDim.x, buf ^= 1) {
        long long base = (long long)c * KB;
        char* tp = dsm + buf * TILE_B;
#pragma unroll
        for (int half = 0; half < 2; half++) {
            float v0[8], v1[8], v2[8];
#pragma unroll
            for (int u = 0; u < 8; u++) {
                long long e = base + w * 16 + half * 8 + u;
                v0[u] = 0.f; v1[u] = 0.f; v2[u] = 0.f;
                if (e < E) {
                    const float* fe = ea + e * 84;
                    if (lane < 4) v0[u] = x[g_col[e] * 4 + lane];
                    else          v0[u] = __ldcs(fe + lane - 4);
                    v1[u] = __ldcs(fe + 28 + lane);
                    if (lane < 24) v2[u] = __ldcs(fe + 60 + lane);
                }
            }
            int ee0 = w * 16 + half * 8;
#pragma unroll
            for (int u = 0; u < 8; u += 2) {
                s0 += v0[u] + v0[u + 1];
                s1 += v1[u] + v1[u + 1];
                s2 += v2[u] + v2[u + 1];
                __nv_bfloat162 b0 = __floats2bfloat162_rn(v0[u], v0[u + 1]);
                __nv_bfloat162 b1 = __floats2bfloat162_rn(v1[u], v1[u + 1]);
                __nv_bfloat162 b2 = (lane < 24) ? __floats2bfloat162_rn(v2[u], v2[u + 1])
                                                : __floats2bfloat162_rn(0.f, 0.f);
                int eo = (ee0 + u) * 2;
                *(__nv_bfloat162*)(tp + lane * ROWB + eo) = b0;
                *(__nv_bfloat162*)(tp + (32 + lane) * ROWB + eo) = b1;
                *(__nv_bfloat162*)(tp + (64 + lane) * ROWB + eo) = b2;
            }
        }
        __syncthreads();
        uint32_t tb = smem_u32(tp);
#pragma unroll
        for (int ks = 0; ks < KB / 16; ks++) {
            uint32_t af[3][4], bf[3][2];
#pragma unroll
            for (int i = 0; i < 3; i++) {
                uint32_t addr = tb + (uint32_t)((Rm + i * 16 + (lane & 15)) * ROWB
                                                + ks * 32 + (lane >> 4) * 16);
                ldm_x4(af[i], addr);
            }
#pragma unroll
            for (int j = 0; j < 3; j++) {
                uint32_t addr = tb + (uint32_t)((Rn + j * 8 + (lane & 7)) * ROWB
                                                + ks * 32 + ((lane >> 3) & 1) * 16);
                ldm_x2(bf[j], addr);
            }
#pragma unroll
            for (int i = 0; i < 3; i++)
#pragma unroll
                for (int j = 0; j < 3; j++) mma_bf16(acc[i][j], af[i], bf[j]);
        }
    }
#pragma unroll
    for (int i = 0; i < 3; i++)
#pragma unroll
        for (int j = 0; j < 3; j++) {
            int row = Rm + i * 16 + (lane >> 2);
            int col = Rn + j * 8 + (lane & 3) * 2;
            atomicAdd(&g_M[row * CH + col], acc[i][j][0]);
            atomicAdd(&g_M[row * CH + col + 1], acc[i][j][1]);
            atomicAdd(&g_M[(row + 8) * CH + col], acc[i][j][2]);
            atomicAdd(&g_M[(row + 8) * CH + col + 1], acc[i][j][3]);
        }
    atomicAdd(&g_sv[lane], s0);
    atomicAdd(&g_sv[32 + lane], s1);
    if (lane < 24) atomicAdd(&g_sv[64 + lane], s2);
}

// ---------------- BN stats --------------------------------------------------
__global__ void k_bn(const float* __restrict__ W1, const float* __restrict__ b1,
                     const float* __restrict__ gamma, float fE) {
    int c = blockIdx.x;
    int t = threadIdx.x;  // 96 threads
    __shared__ float w[CH];
    __shared__ float rq[CH];
    __shared__ float rs[CH];
    w[t] = (t < 88) ? W1[t * OC + c] : 0.f;
    __syncthreads();
    float q = 0.f;
    if (t < 88) {
        const float* Mr = g_M + t * CH;
        for (int k = 0; k < 88; k++) q += Mr[k] * w[k];
        q *= w[t];
    }
    rq[t] = q;
    rs[t] = (t < 88) ? g_sv[t] * w[t] : 0.f;
    __syncthreads();
    if (t == 0) {
        float Q = 0.f, SW = 0.f;
        for (int i = 0; i < 88; i++) { Q += rq[i]; SW += rs[i]; }
        float b = b1[c];
        float mean = SW / fE + b;
        float ex2 = (Q + 2.f * b * SW) / fE + b * b;
        float var = ex2 - mean * mean;
        g_mean[c] = mean;
        g_scale[c] = gamma[c] * rsqrtf(var + EPSV);
    }
}

// ---------------- node output, 4 nodes per warp iteration -------------------
__global__ void k_out(const float* __restrict__ x, const float* __restrict__ W1,
                      const float* __restrict__ b1, const float* __restrict__ beta,
                      const float* __restrict__ W2, const float* __restrict__ b2,
                      float* __restrict__ out, int N) {
    extern __shared__ float sm[];
    float* W1s = sm;             // 88*128
    float* W2s = sm + 88 * OC;   // 132*64
    int tid = threadIdx.x;
    for (int i = tid; i < 88 * OC; i += blockDim.x) W1s[i] = W1[i];
    for (int i = tid; i < 132 * OUTC; i += blockDim.x) W2s[i] = W2[i];
    __syncthreads();
    int lane = tid & 31;
    int warp = (blockIdx.x * blockDim.x + tid) >> 5;
    int nw = (gridDim.x * blockDim.x) >> 5;
    float mn0 = g_mean[lane], mn1 = g_mean[32 + lane], mn2 = g_mean[64 + lane], mn3 = g_mean[96 + lane];
    float sc0 = g_scale[lane], sc1 = g_scale[32 + lane], sc2 = g_scale[64 + lane], sc3 = g_scale[96 + lane];
    float bt0 = beta[lane], bt1 = beta[32 + lane], bt2 = beta[64 + lane], bt3 = beta[96 + lane];
    float bo0 = b1[lane], bo1 = b1[32 + lane], bo2 = b1[64 + lane], bo3 = b1[96 + lane];
    float bb0 = b2[lane], bb1 = b2[32 + lane];

    for (int n0 = warp * 4; n0 < N; n0 += nw * 4) {
        float sr0[4], sr1[4], sr2[4], rcp[4], tv[4];
#pragma unroll
        for (int m = 0; m < 4; m++) {
            int n = n0 + m;
            if (n < N) {
                const float* so = g_S + (size_t)n * CH;
                sr0[m] = so[lane]; sr1[m] = so[32 + lane]; sr2[m] = so[64 + lane];
                int cnt = g_off[n + 1] - g_off[n];
                tv[m] = (cnt > 0) ? 1.f : 0.f;
                rcp[m] = (cnt > 0) ? 1.f / (float)cnt : 0.f;
            } else { sr0[m] = sr1[m] = sr2[m] = 0.f; tv[m] = 0.f; rcp[m] = 0.f; }
        }
        float a0[4] = {0,0,0,0}, a1[4] = {0,0,0,0}, a2[4] = {0,0,0,0}, a3[4] = {0,0,0,0};
#pragma unroll
        for (int cc = 0; cc < 32; cc++) {
            const float* wr = W1s + cc * OC + lane;
            float w0 = wr[0], w1 = wr[32], w2 = wr[64], w3 = wr[96];
#pragma unroll
            for (int m = 0; m < 4; m++) {
                float v = __shfl_sync(0xffffffffu, sr0[m], cc);
                a0[m] += v * w0; a1[m] += v * w1; a2[m] += v * w2; a3[m] += v * w3;
            }
        }
#pragma unroll
        for (int cc = 0; cc < 32; cc++) {
            const float* wr = W1s + (32 + cc) * OC + lane;
            float w0 = wr[0], w1 = wr[32], w2 = wr[64], w3 = wr[96];
#pragma unroll
            for (int m = 0; m < 4; m++) {
                float v = __shfl_sync(0xffffffffu, sr1[m], cc);
                a0[m] += v * w0; a1[m] += v * w1; a2[m] += v * w2; a3[m] += v * w3;
            }
        }
#pragma unroll
        for (int cc = 0; cc < 24; cc++) {
            const float* wr = W1s + (64 + cc) * OC + lane;
            float w0 = wr[0], w1 = wr[32], w2 = wr[64], w3 = wr[96];
#pragma unroll
            for (int m = 0; m < 4; m++) {
                float v = __shfl_sync(0xffffffffu, sr2[m], cc);
                a0[m] += v * w0; a1[m] += v * w1; a2[m] += v * w2; a3[m] += v * w3;
            }
        }
        float ag0[4], ag1[4], ag2[4], ag3[4];
#pragma unroll
        for (int m = 0; m < 4; m++) {
            ag0[m] = ((a0[m] * rcp[m] + bo0 - mn0) * sc0 + bt0) * tv[m];
            ag1[m] = ((a1[m] * rcp[m] + bo1 - mn1) * sc1 + bt1) * tv[m];
            ag2[m] = ((a2[m] * rcp[m] + bo2 - mn2) * sc2 + bt2) * tv[m];
            ag3[m] = ((a3[m] * rcp[m] + bo3 - mn3) * sc3 + bt3) * tv[m];
        }
        float o0[4], o1[4];
#pragma unroll
        for (int m = 0; m < 4; m++) { o0[m] = bb0; o1[m] = bb1; }
#pragma unroll
        for (int k = 0; k < 4; k++) {
            float wa = W2s[k * OUTC + lane], wb = W2s[k * OUTC + 32 + lane];
#pragma unroll
            for (int m = 0; m < 4; m++) {
                int n = n0 + m;
                float xv = (n < N) ? x[(size_t)n * 4 + k] : 0.f;
                o0[m] += xv * wa; o1[m] += xv * wb;
            }
        }
#pragma unroll
        for (int cc = 0; cc < 32; cc++) {
            const float* wr = W2s + (4 + cc) * OUTC + lane;
            float w0 = wr[0], w1 = wr[32];
#pragma unroll
            for (int m = 0; m < 4; m++) {
                float av = __shfl_sync(0xffffffffu, ag0[m], cc);
                o0[m] += av * w0; o1[m] += av * w1;
            }
        }
#pragma unroll
        for (int cc = 0; cc < 32; cc++) {
            const float* wr = W2s + (36 + cc) * OUTC + lane;
            float w0 = wr[0], w1 = wr[32];
#pragma unroll
            for (int m = 0; m < 4; m++) {
                float av = __shfl_sync(0xffffffffu, ag1[m], cc);
                o0[m] += av * w0; o1[m] += av * w1;
            }
        }
#pragma unroll
        for (int cc = 0; cc < 32; cc++) {
            const float* wr = W2s + (68 + cc) * OUTC + lane;
            float w0 = wr[0], w1 = wr[32];
#pragma unroll
            for (int m = 0; m < 4; m++) {
                float av = __shfl_sync(0xffffffffu, ag2[m], cc);
                o0[m] += av * w0; o1[m] += av * w1;
            }
        }
#pragma unroll
        for (int cc = 0; cc < 32; cc++) {
            const float* wr = W2s + (100 + cc) * OUTC + lane;
            float w0 = wr[0], w1 = wr[32];
#pragma unroll
            for (int m = 0; m < 4; m++) {
                float av = __shfl_sync(0xffffffffu, ag3[m], cc);
                o0[m] += av * w0; o1[m] += av * w1;
            }
        }
#pragma unroll
        for (int m = 0; m < 4; m++) {
            int n = n0 + m;
            if (n < N) {
                out[(size_t)n * 64 + lane] = fmaxf(o0[m], 0.f);
                out[(size_t)n * 64 + 32 + lane] = fmaxf(o1[m], 0.f);
            }
        }
    }
}

// ---------------- launcher --------------------------------------------------
extern "C" void kernel_launch(void* const* d_in, const int* in_sizes, int n_in,
                              void* d_out, int out_size) {
    const float* x     = (const float*)d_in[0];
    const void*  ei    = d_in[1];
    const float* ea    = (const float*)d_in[2];
    const float* W1    = (const float*)d_in[3];
    const float* b1    = (const float*)d_in[4];
    const float* gamma = (const float*)d_in[5];
    const float* beta  = (const float*)d_in[6];
    const float* W2    = (const float*)d_in[7];
    const float* b2    = (const float*)d_in[8];
    float* out = (float*)d_out;
    int N = in_sizes[0] / 4;
    int E = in_sizes[2] / 84;
    int nb = (N + SCAN_CH - 1) / SCAN_CH;

    k_detect<<<1, 32>>>(ei);
    k_zero<<<128, 256>>>(N);
    k_convhist<<<512, 256>>>(ei, E);

    // fork AFTER convhist (R7-proven schedule): k_Mmma uses g_col + zeroed g_M
    cudaEventRecord(g_hx.evFork, 0);
    cudaStreamWaitEvent(g_hx.s1, g_hx.evFork, 0);
    const int msmem = 2 * TILE_B;   // 52224 B
    cudaFuncSetAttribute(k_Mmma, cudaFuncAttributeMaxDynamicSharedMemorySize, msmem);
    k_Mmma<<<296, 256, msmem, g_hx.s1>>>(x, ea, E);
    cudaEventRecord(g_hx.evJoin, g_hx.s1);

    // main chain: scan -> perm -> agg
    k_scanA<<<nb, 1024>>>(N);
    k_scanB<<<1, 32>>>(nb, N, E);
    k_scanC<<<(N + 255) / 256, 256>>>(N);
    k_perm<<<512, 256>>>(E);
    k_agg<<<1184, 256>>>(x, ea, N);

    // join: bn needs g_M/g_sv from k_Mmma
    cudaStreamWaitEvent(0, g_hx.evJoin, 0);
    k_bn<<<128, 96>>>(W1, b1, gamma, (float)E);
    const int smem = (88 * OC + 132 * OUTC) * 4;  // 78848 B
    cudaFuncSetAttribute(k_out, cudaFuncAttributeMaxDynamicSharedMemorySize, smem);
    k_out<<<296, 256, smem>>>(x, W1, b1, beta, W2, b2, out, N);
}

// round 11
// speedup vs baseline: 1.5069x; 1.1385x over previous
#include <cuda_runtime.h>
#include <cuda_bf16.h>
#include <cstdint>

#define MAXN 50000
#define MAXE 800000
#define CH 96          // padded feature channels (88 real: 4 x + 84 edge_attr)
#define OC 128
#define OUTC 64
#define EPSV 1e-5f
#define SCAN_CH 2048   // elements per scan CTA

// ---------------- device scratch (static globals: no allocs allowed) -------
__device__ int   g_is64;
__device__ int   g_row[MAXE];
__device__ int   g_col[MAXE];
__device__ int   g_cnt[MAXN];
__device__ int   g_off[MAXN + 1];
__device__ int   g_cur[MAXN];
__device__ int   g_perm[MAXE];
__device__ int   g_srow[MAXE];             // row id in perm order (sorted)
__device__ int   g_blk[64];
__device__ int   g_blkoff[64];
__device__ float g_S[(size_t)MAXN * CH];   // per-node summed features
__device__ float g_M[CH * CH];             // second-moment matrix sum f f^T
__device__ float g_sv[CH];                 // global feature sum s
__device__ float g_mean[OC];
__device__ float g_scale[OC];              // gamma * rsqrt(var+eps)

__device__ __forceinline__ uint32_t smem_u32(const void* p) {
    uint32_t a;
    asm("{ .reg .u64 t; cvta.to.shared.u64 t, %1; cvt.u32.u64 %0, t; }" : "=r"(a) : "l"(p));
    return a;
}

// ---------------- dtype detection: int64 vs int32 edge_index ----------------
__global__ void k_detect(const void* ei) {
    const long long* p = (const long long*)ei;
    int bad = 0;
    for (int i = threadIdx.x; i < 64; i += 32) {
        long long v = p[i];
        if (v < 0 || v >= MAXN) bad = 1;
    }
    unsigned m = __ballot_sync(0xffffffffu, bad);
    if (threadIdx.x == 0) g_is64 = (m == 0) ? 1 : 0;
}

// ---------------- zero scratch (g_cnt, g_M, g_sv, g_S) ----------------------
__global__ void k_zero(int N) {
    int i = blockIdx.x * blockDim.x + threadIdx.x;
    int T = gridDim.x * blockDim.x;
    for (int j = i; j < N; j += T) g_cnt[j] = 0;
    for (int j = i; j < CH * CH; j += T) g_M[j] = 0.f;
    size_t tot = (size_t)N * CH;
    for (size_t j = i; j < tot; j += T) g_S[j] = 0.f;
    if (i < CH) g_sv[i] = 0.f;
}

// ---------------- convert + histogram fused ---------------------------------
__global__ void k_convhist(const void* ei, int E) {
    int is64 = g_is64;
    int i = blockIdx.x * blockDim.x + threadIdx.x;
    int T = gridDim.x * blockDim.x;
    if (is64) {
        const long long* p = (const long long*)ei;
        for (int e = i; e < E; e += T) {
            int r = (int)p[e];
            g_row[e] = r; g_col[e] = (int)p[E + e];
            atomicAdd(&g_cnt[r], 1);
        }
    } else {
        const int* p = (const int*)ei;
        for (int e = i; e < E; e += T) {
            int r = p[e];
            g_row[e] = r; g_col[e] = p[E + e];
            atomicAdd(&g_cnt[r], 1);
        }
    }
}

// ---------------- multi-CTA exclusive scan ----------------------------------
__global__ void k_scanA(int N) {
    __shared__ int sc[1024];
    int b = blockIdx.x, t = threadIdx.x;
    int i0 = b * SCAN_CH + t * 2;
    int c0 = (i0 < N) ? g_cnt[i0] : 0;
    int c1 = (i0 + 1 < N) ? g_cnt[i0 + 1] : 0;
    int s = c0 + c1;
    sc[t] = s;
    __syncthreads();
#pragma unroll
    for (int d = 1; d < 1024; d <<= 1) {
        int v = (t >= d) ? sc[t - d] : 0;
        __syncthreads();
        sc[t] += v;
        __syncthreads();
    }
    int excl = sc[t] - s;
    if (i0 < N) g_off[i0] = excl;
    if (i0 + 1 < N) g_off[i0 + 1] = excl + c0;
    if (t == 1023) g_blk[b] = sc[1023];
}

__global__ void k_scanB(int nb, int N, int E) {
    int t = threadIdx.x;
    int v = (t < nb) ? g_blk[t] : 0;
    int incl = v;
#pragma unroll
    for (int d = 1; d < 32; d <<= 1) {
        int u = __shfl_up_sync(0xffffffffu, incl, d);
        if (t >= d) incl += u;
    }
    if (t < nb) g_blkoff[t] = incl - v;
    if (t == 0) g_off[N] = E;
}

__global__ void k_scanC(int N) {
    int i = blockIdx.x * blockDim.x + threadIdx.x;
    if (i < N) {
        int v = g_off[i] + g_blkoff[i >> 11];
        g_off[i] = v;
        g_cur[i] = v;
    }
}

__global__ void k_perm(int E) {
    int i = blockIdx.x * blockDim.x + threadIdx.x;
    int T = gridDim.x * blockDim.x;
    for (int e = i; e < E; e += T) {
        int r = g_row[e];
        int p = atomicAdd(&g_cur[r], 1);
        g_perm[p] = e;
        g_srow[p] = r;
    }
}

// ---------------- FUSED: M = sum f f^T (HMMA) + per-node S (seg-reduce) ----
// Edges consumed in perm (row-sorted) order: single pass over edge_attr.
// Double-buffered 96x128 bf16 tiles; warps 2x4, 48x24 output each.
// Per-lane segmented sums flushed with coalesced atomicAdd on row change.
#define KB 128
#define ROWB 272
#define TILE_B (CH * ROWB)   // 26112

__device__ __forceinline__ void ldm_x4(uint32_t* r, uint32_t a) {
    asm volatile("ldmatrix.sync.aligned.m8n8.x4.shared.b16 {%0,%1,%2,%3}, [%4];"
                 : "=r"(r[0]), "=r"(r[1]), "=r"(r[2]), "=r"(r[3]) : "r"(a));
}
__device__ __forceinline__ void ldm_x2(uint32_t* r, uint32_t a) {
    asm volatile("ldmatrix.sync.aligned.m8n8.x2.shared.b16 {%0,%1}, [%2];"
                 : "=r"(r[0]), "=r"(r[1]) : "r"(a));
}
__device__ __forceinline__ void mma_bf16(float* c, const uint32_t* a, const uint32_t* b) {
    asm volatile("mma.sync.aligned.m16n8k16.row.col.f32.bf16.bf16.f32 "
                 "{%0,%1,%2,%3}, {%4,%5,%6,%7}, {%8,%9}, {%0,%1,%2,%3};"
                 : "+f"(c[0]), "+f"(c[1]), "+f"(c[2]), "+f"(c[3])
                 : "r"(a[0]), "r"(a[1]), "r"(a[2]), "r"(a[3]), "r"(b[0]), "r"(b[1]));
}

__global__ void __launch_bounds__(256, 2)
k_fused(const float* __restrict__ x, const float* __restrict__ ea, int E) {
    extern __shared__ __align__(16) char dsm[];   // 2 * TILE_B
    int tid = threadIdx.x;
    int lane = tid & 31, w = tid >> 5;
    int warp_m = w >> 2, warp_n = w & 3;   // 2 x 4
    int Rm = warp_m * 48;                  // 3 x 16 rows
    int Rn = warp_n * 24;                  // 3 x 8 cols

    float acc[3][3][4];
#pragma unroll
    for (int i = 0; i < 3; i++)
#pragma unroll
        for (int j = 0; j < 3; j++)
#pragma unroll
            for (int q = 0; q < 4; q++) acc[i][j][q] = 0.f;

    float s0 = 0.f, s1 = 0.f, s2 = 0.f;
    // segmented per-node sums (lane holds one channel per group)
    float aS0 = 0.f, aS1 = 0.f, aS2 = 0.f;
    int curRow = -1;

    int nchunk = (E + KB - 1) / KB;
    int buf = 0;
    for (int c = blockIdx.x; c < nchunk; c += gridDim.x, buf ^= 1) {
        long long base = (long long)c * KB;
        char* tp = dsm + buf * TILE_B;
#pragma unroll
        for (int half = 0; half < 2; half++) {
            float v0[8], v1[8], v2[8];
            int rw[8];
#pragma unroll
            for (int u = 0; u < 8; u++) {
                long long idx = base + w * 16 + half * 8 + u;
                int ok = idx < E;
                long long ide = ok ? idx : (long long)(E - 1);
                int e = g_perm[ide];
                rw[u] = g_srow[ide];
                const float* fe = ea + (size_t)e * 84;
                float p, q, r;
                if (lane < 4) p = x[g_col[e] * 4 + lane];
                else          p = __ldcs(fe + lane - 4);
                q = __ldcs(fe + 28 + lane);
                r = (lane < 24) ? __ldcs(fe + 60 + lane) : 0.f;
                float m = ok ? 1.f : 0.f;
                v0[u] = m * p; v1[u] = m * q; v2[u] = m * r;
            }
            int ee0 = w * 16 + half * 8;
#pragma unroll
            for (int u = 0; u < 8; u += 2) {
                s0 += v0[u] + v0[u + 1];
                s1 += v1[u] + v1[u + 1];
                s2 += v2[u] + v2[u + 1];
                __nv_bfloat162 b0 = __floats2bfloat162_rn(v0[u], v0[u + 1]);
                __nv_bfloat162 b1 = __floats2bfloat162_rn(v1[u], v1[u + 1]);
                __nv_bfloat162 b2 = __floats2bfloat162_rn(v2[u], v2[u + 1]);
                int eo = (ee0 + u) * 2;
                *(__nv_bfloat162*)(tp + lane * ROWB + eo) = b0;
                *(__nv_bfloat162*)(tp + (32 + lane) * ROWB + eo) = b1;
                *(__nv_bfloat162*)(tp + (64 + lane) * ROWB + eo) = b2;
            }
            // segmented reduce (rw warp-uniform per u)
#pragma unroll
            for (int u = 0; u < 8; u++) {
                if (rw[u] != curRow) {
                    if (curRow >= 0) {
                        float* dst = g_S + (size_t)curRow * CH;
                        atomicAdd(&dst[lane], aS0);
                        atomicAdd(&dst[32 + lane], aS1);
                        if (lane < 24) atomicAdd(&dst[64 + lane], aS2);
                    }
                    curRow = rw[u];
                    aS0 = 0.f; aS1 = 0.f; aS2 = 0.f;
                }
                aS0 += v0[u]; aS1 += v1[u]; aS2 += v2[u];
            }
        }
        __syncthreads();
        uint32_t tb = smem_u32(tp);
#pragma unroll
        for (int ks = 0; ks < KB / 16; ks++) {
            uint32_t af[3][4], bf[3][2];
#pragma unroll
            for (int i = 0; i < 3; i++) {
                uint32_t addr = tb + (uint32_t)((Rm + i * 16 + (lane & 15)) * ROWB
                                                + ks * 32 + (lane >> 4) * 16);
                ldm_x4(af[i], addr);
            }
#pragma unroll
            for (int j = 0; j < 3; j++) {
                uint32_t addr = tb + (uint32_t)((Rn + j * 8 + (lane & 7)) * ROWB
                                                + ks * 32 + ((lane >> 3) & 1) * 16);
                ldm_x2(bf[j], addr);
            }
#pragma unroll
            for (int i = 0; i < 3; i++)
#pragma unroll
                for (int j = 0; j < 3; j++) mma_bf16(acc[i][j], af[i], bf[j]);
        }
    }
    // final segment flush
    if (curRow >= 0) {
        float* dst = g_S + (size_t)curRow * CH;
        atomicAdd(&dst[lane], aS0);
        atomicAdd(&dst[32 + lane], aS1);
        if (lane < 24) atomicAdd(&dst[64 + lane], aS2);
    }
    // M writeback
#pragma unroll
    for (int i = 0; i < 3; i++)
#pragma unroll
        for (int j = 0; j < 3; j++) {
            int row = Rm + i * 16 + (lane >> 2);
            int col = Rn + j * 8 + (lane & 3) * 2;
            atomicAdd(&g_M[row * CH + col], acc[i][j][0]);
            atomicAdd(&g_M[row * CH + col + 1], acc[i][j][1]);
            atomicAdd(&g_M[(row + 8) * CH + col], acc[i][j][2]);
            atomicAdd(&g_M[(row + 8) * CH + col + 1], acc[i][j][3]);
        }
    atomicAdd(&g_sv[lane], s0);
    atomicAdd(&g_sv[32 + lane], s1);
    if (lane < 24) atomicAdd(&g_sv[64 + lane], s2);
}

// ---------------- BN stats --------------------------------------------------
__global__ void k_bn(const float* __restrict__ W1, const float* __restrict__ b1,
                     const float* __restrict__ gamma, float fE) {
    int c = blockIdx.x;
    int t = threadIdx.x;  // 96 threads
    __shared__ float w[CH];
    __shared__ float rq[CH];
    __shared__ float rs[CH];
    w[t] = (t < 88) ? W1[t * OC + c] : 0.f;
    __syncthreads();
    float q = 0.f;
    if (t < 88) {
        const float* Mr = g_M + t * CH;
        for (int k = 0; k < 88; k++) q += Mr[k] * w[k];
        q *= w[t];
    }
    rq[t] = q;
    rs[t] = (t < 88) ? g_sv[t] * w[t] : 0.f;
    __syncthreads();
    if (t == 0) {
        float Q = 0.f, SW = 0.f;
        for (int i = 0; i < 88; i++) { Q += rq[i]; SW += rs[i]; }
        float b = b1[c];
        float mean = SW / fE + b;
        float ex2 = (Q + 2.f * b * SW) / fE + b * b;
        float var = ex2 - mean * mean;
        g_mean[c] = mean;
        g_scale[c] = gamma[c] * rsqrtf(var + EPSV);
    }
}

// ---------------- node output, 4 nodes per warp iteration -------------------
__global__ void k_out(const float* __restrict__ x, const float* __restrict__ W1,
                      const float* __restrict__ b1, const float* __restrict__ beta,
                      const float* __restrict__ W2, const float* __restrict__ b2,
                      float* __restrict__ out, int N) {
    extern __shared__ float sm[];
    float* W1s = sm;             // 88*128
    float* W2s = sm + 88 * OC;   // 132*64
    int tid = threadIdx.x;
    for (int i = tid; i < 88 * OC; i += blockDim.x) W1s[i] = W1[i];
    for (int i = tid; i < 132 * OUTC; i += blockDim.x) W2s[i] = W2[i];
    __syncthreads();
    int lane = tid & 31;
    int warp = (blockIdx.x * blockDim.x + tid) >> 5;
    int nw = (gridDim.x * blockDim.x) >> 5;
    float mn0 = g_mean[lane], mn1 = g_mean[32 + lane], mn2 = g_mean[64 + lane], mn3 = g_mean[96 + lane];
    float sc0 = g_scale[lane], sc1 = g_scale[32 + lane], sc2 = g_scale[64 + lane], sc3 = g_scale[96 + lane];
    float bt0 = beta[lane], bt1 = beta[32 + lane], bt2 = beta[64 + lane], bt3 = beta[96 + lane];
    float bo0 = b1[lane], bo1 = b1[32 + lane], bo2 = b1[64 + lane], bo3 = b1[96 + lane];
    float bb0 = b2[lane], bb1 = b2[32 + lane];

    for (int n0 = warp * 4; n0 < N; n0 += nw * 4) {
        float sr0[4], sr1[4], sr2[4], rcp[4], tv[4];
#pragma unroll
        for (int m = 0; m < 4; m++) {
            int n = n0 + m;
            if (n < N) {
                const float* so = g_S + (size_t)n * CH;
                sr0[m] = so[lane]; sr1[m] = so[32 + lane]; sr2[m] = so[64 + lane];
                int cnt = g_off[n + 1] - g_off[n];
                tv[m] = (cnt > 0) ? 1.f : 0.f;
                rcp[m] = (cnt > 0) ? 1.f / (float)cnt : 0.f;
            } else { sr0[m] = sr1[m] = sr2[m] = 0.f; tv[m] = 0.f; rcp[m] = 0.f; }
        }
        float a0[4] = {0,0,0,0}, a1[4] = {0,0,0,0}, a2[4] = {0,0,0,0}, a3[4] = {0,0,0,0};
#pragma unroll
        for (int cc = 0; cc < 32; cc++) {
            const float* wr = W1s + cc * OC + lane;
            float w0 = wr[0], w1 = wr[32], w2 = wr[64], w3 = wr[96];
#pragma unroll
            for (int m = 0; m < 4; m++) {
                float v = __shfl_sync(0xffffffffu, sr0[m], cc);
                a0[m] += v * w0; a1[m] += v * w1; a2[m] += v * w2; a3[m] += v * w3;
            }
        }
#pragma unroll
        for (int cc = 0; cc < 32; cc++) {
            const float* wr = W1s + (32 + cc) * OC + lane;
            float w0 = wr[0], w1 = wr[32], w2 = wr[64], w3 = wr[96];
#pragma unroll
            for (int m = 0; m < 4; m++) {
                float v = __shfl_sync(0xffffffffu, sr1[m], cc);
                a0[m] += v * w0; a1[m] += v * w1; a2[m] += v * w2; a3[m] += v * w3;
            }
        }
#pragma unroll
        for (int cc = 0; cc < 24; cc++) {
            const float* wr = W1s + (64 + cc) * OC + lane;
            float w0 = wr[0], w1 = wr[32], w2 = wr[64], w3 = wr[96];
#pragma unroll
            for (int m = 0; m < 4; m++) {
                float v = __shfl_sync(0xffffffffu, sr2[m], cc);
                a0[m] += v * w0; a1[m] += v * w1; a2[m] += v * w2; a3[m] += v * w3;
            }
        }
        float ag0[4], ag1[4], ag2[4], ag3[4];
#pragma unroll
        for (int m = 0; m < 4; m++) {
            ag0[m] = ((a0[m] * rcp[m] + bo0 - mn0) * sc0 + bt0) * tv[m];
            ag1[m] = ((a1[m] * rcp[m] + bo1 - mn1) * sc1 + bt1) * tv[m];
            ag2[m] = ((a2[m] * rcp[m] + bo2 - mn2) * sc2 + bt2) * tv[m];
            ag3[m] = ((a3[m] * rcp[m] + bo3 - mn3) * sc3 + bt3) * tv[m];
        }
        float o0[4], o1[4];
#pragma unroll
        for (int m = 0; m < 4; m++) { o0[m] = bb0; o1[m] = bb1; }
#pragma unroll
        for (int k = 0; k < 4; k++) {
            float wa = W2s[k * OUTC + lane], wb = W2s[k * OUTC + 32 + lane];
#pragma unroll
            for (int m = 0; m < 4; m++) {
                int n = n0 + m;
                float xv = (n < N) ? x[(size_t)n * 4 + k] : 0.f;
                o0[m] += xv * wa; o1[m] += xv * wb;
            }
        }
#pragma unroll
        for (int cc = 0; cc < 32; cc++) {
            const float* wr = W2s + (4 + cc) * OUTC + lane;
            float w0 = wr[0], w1 = wr[32];
#pragma unroll
            for (int m = 0; m < 4; m++) {
                float av = __shfl_sync(0xffffffffu, ag0[m], cc);
                o0[m] += av * w0; o1[m] += av * w1;
            }
        }
#pragma unroll
        for (int cc = 0; cc < 32; cc++) {
            const float* wr = W2s + (36 + cc) * OUTC + lane;
            float w0 = wr[0], w1 = wr[32];
#pragma unroll
            for (int m = 0; m < 4; m++) {
                float av = __shfl_sync(0xffffffffu, ag1[m], cc);
                o0[m] += av * w0; o1[m] += av * w1;
            }
        }
#pragma unroll
        for (int cc = 0; cc < 32; cc++) {
            const float* wr = W2s + (68 + cc) * OUTC + lane;
            float w0 = wr[0], w1 = wr[32];
#pragma unroll
            for (int m = 0; m < 4; m++) {
                float av = __shfl_sync(0xffffffffu, ag2[m], cc);
                o0[m] += av * w0; o1[m] += av * w1;
            }
        }
#pragma unroll
        for (int cc = 0; cc < 32; cc++) {
            const float* wr = W2s + (100 + cc) * OUTC + lane;
            float w0 = wr[0], w1 = wr[32];
#pragma unroll
            for (int m = 0; m < 4; m++) {
                float av = __shfl_sync(0xffffffffu, ag3[m], cc);
                o0[m] += av * w0; o1[m] += av * w1;
            }
        }
#pragma unroll
        for (int m = 0; m < 4; m++) {
            int n = n0 + m;
            if (n < N) {
                out[(size_t)n * 64 + lane] = fmaxf(o0[m], 0.f);
                out[(size_t)n * 64 + 32 + lane] = fmaxf(o1[m], 0.f);
            }
        }
    }
}

// ---------------- launcher --------------------------------------------------
extern "C" void kernel_launch(void* const* d_in, const int* in_sizes, int n_in,
                              void* d_out, int out_size) {
    const float* x     = (const float*)d_in[0];
    const void*  ei    = d_in[1];
    const float* ea    = (const float*)d_in[2];
    const float* W1    = (const float*)d_in[3];
    const float* b1    = (const float*)d_in[4];
    const float* gamma = (const float*)d_in[5];
    const float* beta  = (const float*)d_in[6];
    const float* W2    = (const float*)d_in[7];
    const float* b2    = (const float*)d_in[8];
    float* out = (float*)d_out;
    int N = in_sizes[0] / 4;
    int E = in_sizes[2] / 84;
    int nb = (N + SCAN_CH - 1) / SCAN_CH;

    k_detect<<<1, 32>>>(ei);
    k_zero<<<512, 256>>>(N);
    k_convhist<<<512, 256>>>(ei, E);
    k_scanA<<<nb, 1024>>>(N);
    k_scanB<<<1, 32>>>(nb, N, E);
    k_scanC<<<(N + 255) / 256, 256>>>(N);
    k_perm<<<512, 256>>>(E);

    const int msmem = 2 * TILE_B;   // 52224 B
    cudaFuncSetAttribute(k_fused, cudaFuncAttributeMaxDynamicSharedMemorySize, msmem);
    k_fused<<<296, 256, msmem>>>(x, ea, E);

    k_bn<<<128, 96>>>(W1, b1, gamma, (float)E);
    const int smem = (88 * OC + 132 * OUTC) * 4;  // 78848 B
    cudaFuncSetAttribute(k_out, cudaFuncAttributeMaxDynamicSharedMemorySize, smem);
    k_out<<<296, 256, smem>>>(x, W1, b1, beta, W2, b2, out, N);
}

// round 12
// speedup vs baseline: 1.5338x; 1.0178x over previous
#include <cuda_runtime.h>
#include <cuda_bf16.h>
#include <cstdint>

#define MAXN 50000
#define MAXE 800000
#define CH 96          // padded feature channels (88 real: 4 x + 84 edge_attr)
#define OC 128
#define OUTC 64
#define EPSV 1e-5f
#define SCAN_CH 2048   // elements per scan CTA

// ---------------- device scratch (static globals: no allocs allowed) -------
__device__ int   g_is64;
__device__ int   g_row[MAXE];
__device__ int   g_col[MAXE];
__device__ int   g_cnt[MAXN];
__device__ int   g_off[MAXN + 1];
__device__ int   g_cur[MAXN];
__device__ int   g_perm[MAXE];
__device__ int   g_srow[MAXE];             // row id in perm order (sorted)
__device__ int   g_blk[64];
__device__ int   g_blkoff[64];
__device__ float g_S[(size_t)MAXN * CH];   // per-node summed features
__device__ float g_M[CH * CH];             // second-moment matrix sum f f^T
__device__ float g_sv[CH];                 // global feature sum s
__device__ float g_mean[OC];
__device__ float g_scale[OC];              // gamma * rsqrt(var+eps)

__device__ __forceinline__ uint32_t smem_u32(const void* p) {
    uint32_t a;
    asm("{ .reg .u64 t; cvta.to.shared.u64 t, %1; cvt.u32.u64 %0, t; }" : "=r"(a) : "l"(p));
    return a;
}
__device__ __forceinline__ void fma2(unsigned long long& d,
                                     unsigned long long a, unsigned long long b) {
    asm("fma.rn.f32x2 %0, %1, %2, %0;" : "+l"(d) : "l"(a), "l"(b));
}
__device__ __forceinline__ unsigned long long packdup(float v) {
    unsigned long long r;
    asm("mov.b64 %0, {%1, %1};" : "=l"(r) : "f"(v));
    return r;
}
__device__ __forceinline__ unsigned long long pack2(float lo, float hi) {
    unsigned long long r;
    asm("mov.b64 %0, {%1, %2};" : "=l"(r) : "f"(lo), "f"(hi));
    return r;
}

// ---------------- dtype detection: int64 vs int32 edge_index ----------------
__global__ void k_detect(const void* ei) {
    const long long* p = (const long long*)ei;
    int bad = 0;
    for (int i = threadIdx.x; i < 64; i += 32) {
        long long v = p[i];
        if (v < 0 || v >= MAXN) bad = 1;
    }
    unsigned m = __ballot_sync(0xffffffffu, bad);
    if (threadIdx.x == 0) g_is64 = (m == 0) ? 1 : 0;
}

// ---------------- zero scratch (g_cnt, g_M, g_sv, g_S) ----------------------
__global__ void k_zero(int N) {
    int i = blockIdx.x * blockDim.x + threadIdx.x;
    int T = gridDim.x * blockDim.x;
    for (int j = i; j < N; j += T) g_cnt[j] = 0;
    for (int j = i; j < CH * CH; j += T) g_M[j] = 0.f;
    size_t tot = (size_t)N * CH;
    for (size_t j = i; j < tot; j += T) g_S[j] = 0.f;
    if (i < CH) g_sv[i] = 0.f;
}

// ---------------- convert + histogram fused ---------------------------------
__global__ void k_convhist(const void* ei, int E) {
    int is64 = g_is64;
    int i = blockIdx.x * blockDim.x + threadIdx.x;
    int T = gridDim.x * blockDim.x;
    if (is64) {
        const long long* p = (const long long*)ei;
        for (int e = i; e < E; e += T) {
            int r = (int)p[e];
            g_row[e] = r; g_col[e] = (int)p[E + e];
            atomicAdd(&g_cnt[r], 1);
        }
    } else {
        const int* p = (const int*)ei;
        for (int e = i; e < E; e += T) {
            int r = p[e];
            g_row[e] = r; g_col[e] = p[E + e];
            atomicAdd(&g_cnt[r], 1);
        }
    }
}

// ---------------- multi-CTA exclusive scan ----------------------------------
__global__ void k_scanA(int N) {
    __shared__ int sc[1024];
    int b = blockIdx.x, t = threadIdx.x;
    int i0 = b * SCAN_CH + t * 2;
    int c0 = (i0 < N) ? g_cnt[i0] : 0;
    int c1 = (i0 + 1 < N) ? g_cnt[i0 + 1] : 0;
    int s = c0 + c1;
    sc[t] = s;
    __syncthreads();
#pragma unroll
    for (int d = 1; d < 1024; d <<= 1) {
        int v = (t >= d) ? sc[t - d] : 0;
        __syncthreads();
        sc[t] += v;
        __syncthreads();
    }
    int excl = sc[t] - s;
    if (i0 < N) g_off[i0] = excl;
    if (i0 + 1 < N) g_off[i0 + 1] = excl + c0;
    if (t == 1023) g_blk[b] = sc[1023];
}

__global__ void k_scanB(int nb, int N, int E) {
    int t = threadIdx.x;
    int v = (t < nb) ? g_blk[t] : 0;
    int incl = v;
#pragma unroll
    for (int d = 1; d < 32; d <<= 1) {
        int u = __shfl_up_sync(0xffffffffu, incl, d);
        if (t >= d) incl += u;
    }
    if (t < nb) g_blkoff[t] = incl - v;
    if (t == 0) g_off[N] = E;
}

__global__ void k_scanC(int N) {
    int i = blockIdx.x * blockDim.x + threadIdx.x;
    if (i < N) {
        int v = g_off[i] + g_blkoff[i >> 11];
        g_off[i] = v;
        g_cur[i] = v;
    }
}

__global__ void k_perm(int E) {
    int i = blockIdx.x * blockDim.x + threadIdx.x;
    int T = gridDim.x * blockDim.x;
    for (int e = i; e < E; e += T) {
        int r = g_row[e];
        int p = atomicAdd(&g_cur[r], 1);
        g_perm[p] = e;
        g_srow[p] = r;
    }
}

// ---------------- FUSED: M = sum f f^T (HMMA) + per-node S (seg-reduce) ----
#define KB 128
#define ROWB 272
#define TILE_B (CH * ROWB)   // 26112

__device__ __forceinline__ void ldm_x4(uint32_t* r, uint32_t a) {
    asm volatile("ldmatrix.sync.aligned.m8n8.x4.shared.b16 {%0,%1,%2,%3}, [%4];"
                 : "=r"(r[0]), "=r"(r[1]), "=r"(r[2]), "=r"(r[3]) : "r"(a));
}
__device__ __forceinline__ void ldm_x2(uint32_t* r, uint32_t a) {
    asm volatile("ldmatrix.sync.aligned.m8n8.x2.shared.b16 {%0,%1}, [%2];"
                 : "=r"(r[0]), "=r"(r[1]) : "r"(a));
}
__device__ __forceinline__ void mma_bf16(float* c, const uint32_t* a, const uint32_t* b) {
    asm volatile("mma.sync.aligned.m16n8k16.row.col.f32.bf16.bf16.f32 "
                 "{%0,%1,%2,%3}, {%4,%5,%6,%7}, {%8,%9}, {%0,%1,%2,%3};"
                 : "+f"(c[0]), "+f"(c[1]), "+f"(c[2]), "+f"(c[3])
                 : "r"(a[0]), "r"(a[1]), "r"(a[2]), "r"(a[3]), "r"(b[0]), "r"(b[1]));
}

__global__ void __launch_bounds__(256, 2)
k_fused(const float* __restrict__ x, const float* __restrict__ ea, int E) {
    extern __shared__ __align__(16) char dsm[];   // 2 * TILE_B
    int tid = threadIdx.x;
    int lane = tid & 31, w = tid >> 5;
    int warp_m = w >> 2, warp_n = w & 3;   // 2 x 4
    int Rm = warp_m * 48;                  // 3 x 16 rows
    int Rn = warp_n * 24;                  // 3 x 8 cols

    float acc[3][3][4];
#pragma unroll
    for (int i = 0; i < 3; i++)
#pragma unroll
        for (int j = 0; j < 3; j++)
#pragma unroll
            for (int q = 0; q < 4; q++) acc[i][j][q] = 0.f;

    float s0 = 0.f, s1 = 0.f, s2 = 0.f;
    float aS0 = 0.f, aS1 = 0.f, aS2 = 0.f;
    int curRow = -1;

    int nchunk = (E + KB - 1) / KB;
    int buf = 0;
    for (int c = blockIdx.x; c < nchunk; c += gridDim.x, buf ^= 1) {
        long long base = (long long)c * KB;
        char* tp = dsm + buf * TILE_B;
#pragma unroll
        for (int half = 0; half < 2; half++) {
            float v0[8], v1[8], v2[8];
            int rw[8];
#pragma unroll
            for (int u = 0; u < 8; u++) {
                long long idx = base + w * 16 + half * 8 + u;
                int ok = idx < E;
                long long ide = ok ? idx : (long long)(E - 1);
                int e = g_perm[ide];
                rw[u] = g_srow[ide];
                const float* fe = ea + (size_t)e * 84;
                float p, q, r;
                if (lane < 4) p = x[g_col[e] * 4 + lane];
                else          p = __ldcs(fe + lane - 4);
                q = __ldcs(fe + 28 + lane);
                r = (lane < 24) ? __ldcs(fe + 60 + lane) : 0.f;
                float m = ok ? 1.f : 0.f;
                v0[u] = m * p; v1[u] = m * q; v2[u] = m * r;
            }
            int ee0 = w * 16 + half * 8;
#pragma unroll
            for (int u = 0; u < 8; u += 2) {
                s0 += v0[u] + v0[u + 1];
                s1 += v1[u] + v1[u + 1];
                s2 += v2[u] + v2[u + 1];
                __nv_bfloat162 b0 = __floats2bfloat162_rn(v0[u], v0[u + 1]);
                __nv_bfloat162 b1 = __floats2bfloat162_rn(v1[u], v1[u + 1]);
                __nv_bfloat162 b2 = __floats2bfloat162_rn(v2[u], v2[u + 1]);
                int eo = (ee0 + u) * 2;
                *(__nv_bfloat162*)(tp + lane * ROWB + eo) = b0;
                *(__nv_bfloat162*)(tp + (32 + lane) * ROWB + eo) = b1;
                *(__nv_bfloat162*)(tp + (64 + lane) * ROWB + eo) = b2;
            }
#pragma unroll
            for (int u = 0; u < 8; u++) {
                if (rw[u] != curRow) {
                    if (curRow >= 0) {
                        float* dst = g_S + (size_t)curRow * CH;
                        atomicAdd(&dst[lane], aS0);
                        atomicAdd(&dst[32 + lane], aS1);
                        if (lane < 24) atomicAdd(&dst[64 + lane], aS2);
                    }
                    curRow = rw[u];
                    aS0 = 0.f; aS1 = 0.f; aS2 = 0.f;
                }
                aS0 += v0[u]; aS1 += v1[u]; aS2 += v2[u];
            }
        }
        __syncthreads();
        uint32_t tb = smem_u32(tp);
#pragma unroll
        for (int ks = 0; ks < KB / 16; ks++) {
            uint32_t af[3][4], bf[3][2];
#pragma unroll
            for (int i = 0; i < 3; i++) {
                uint32_t addr = tb + (uint32_t)((Rm + i * 16 + (lane & 15)) * ROWB
                                                + ks * 32 + (lane >> 4) * 16);
                ldm_x4(af[i], addr);
            }
#pragma unroll
            for (int j = 0; j < 3; j++) {
                uint32_t addr = tb + (uint32_t)((Rn + j * 8 + (lane & 7)) * ROWB
                                                + ks * 32 + ((lane >> 3) & 1) * 16);
                ldm_x2(bf[j], addr);
            }
#pragma unroll
            for (int i = 0; i < 3; i++)
#pragma unroll
                for (int j = 0; j < 3; j++) mma_bf16(acc[i][j], af[i], bf[j]);
        }
    }
    if (curRow >= 0) {
        float* dst = g_S + (size_t)curRow * CH;
        atomicAdd(&dst[lane], aS0);
        atomicAdd(&dst[32 + lane], aS1);
        if (lane < 24) atomicAdd(&dst[64 + lane], aS2);
    }
#pragma unroll
    for (int i = 0; i < 3; i++)
#pragma unroll
        for (int j = 0; j < 3; j++) {
            int row = Rm + i * 16 + (lane >> 2);
            int col = Rn + j * 8 + (lane & 3) * 2;
            atomicAdd(&g_M[row * CH + col], acc[i][j][0]);
            atomicAdd(&g_M[row * CH + col + 1], acc[i][j][1]);
            atomicAdd(&g_M[(row + 8) * CH + col], acc[i][j][2]);
            atomicAdd(&g_M[(row + 8) * CH + col + 1], acc[i][j][3]);
        }
    atomicAdd(&g_sv[lane], s0);
    atomicAdd(&g_sv[32 + lane], s1);
    if (lane < 24) atomicAdd(&g_sv[64 + lane], s2);
}

// ---------------- BN stats --------------------------------------------------
__global__ void k_bn(const float* __restrict__ W1, const float* __restrict__ b1,
                     const float* __restrict__ gamma, float fE) {
    int c = blockIdx.x;
    int t = threadIdx.x;  // 96 threads
    __shared__ float w[CH];
    __shared__ float rq[CH];
    __shared__ float rs[CH];
    w[t] = (t < 88) ? W1[t * OC + c] : 0.f;
    __syncthreads();
    float q = 0.f;
    if (t < 88) {
        const float* Mr = g_M + t * CH;
        for (int k = 0; k < 88; k++) q += Mr[k] * w[k];
        q *= w[t];
    }
    rq[t] = q;
    rs[t] = (t < 88) ? g_sv[t] * w[t] : 0.f;
    __syncthreads();
    if (t == 0) {
        float Q = 0.f, SW = 0.f;
        for (int i = 0; i < 88; i++) { Q += rq[i]; SW += rs[i]; }
        float b = b1[c];
        float mean = SW / fE + b;
        float ex2 = (Q + 2.f * b * SW) / fE + b * b;
        float var = ex2 - mean * mean;
        g_mean[c] = mean;
        g_scale[c] = gamma[c] * rsqrtf(var + EPSV);
    }
}

// ---------------- node output: f32x2 packed math, 4 nodes per warp ----------
// smem layout (float2):
//   W1pA[88*32]: (W1[cc,lane],  W1[cc,32+lane])
//   W1pB[88*32]: (W1[cc,64+lane],W1[cc,96+lane])
//   W2p [132*32]: (W2[cc,lane],  W2[cc,32+lane])
__global__ void k_out(const float* __restrict__ x, const float* __restrict__ W1,
                      const float* __restrict__ b1, const float* __restrict__ beta,
                      const float* __restrict__ W2, const float* __restrict__ b2,
                      float* __restrict__ out, int N) {
    extern __shared__ float2 smp[];
    float2* W1pA = smp;                // 2816
    float2* W1pB = smp + 88 * 32;      // 2816
    float2* W2p  = smp + 2 * 88 * 32;  // 4224
    int tid = threadIdx.x;
    for (int i = tid; i < 88 * 32; i += blockDim.x) {
        int cc = i >> 5, l = i & 31;
        W1pA[i] = make_float2(W1[cc * OC + l], W1[cc * OC + 32 + l]);
        W1pB[i] = make_float2(W1[cc * OC + 64 + l], W1[cc * OC + 96 + l]);
    }
    for (int i = tid; i < 132 * 32; i += blockDim.x) {
        int cc = i >> 5, l = i & 31;
        W2p[i] = make_float2(W2[cc * OUTC + l], W2[cc * OUTC + 32 + l]);
    }
    __syncthreads();
    int lane = tid & 31;
    int warp = (blockIdx.x * blockDim.x + tid) >> 5;
    int nw = (gridDim.x * blockDim.x) >> 5;
    float mn0 = g_mean[lane], mn1 = g_mean[32 + lane], mn2 = g_mean[64 + lane], mn3 = g_mean[96 + lane];
    float sc0 = g_scale[lane], sc1 = g_scale[32 + lane], sc2 = g_scale[64 + lane], sc3 = g_scale[96 + lane];
    float bt0 = beta[lane], bt1 = beta[32 + lane], bt2 = beta[64 + lane], bt3 = beta[96 + lane];
    float bo0 = b1[lane], bo1 = b1[32 + lane], bo2 = b1[64 + lane], bo3 = b1[96 + lane];
    float bb0 = b2[lane], bb1 = b2[32 + lane];
    unsigned long long bbP = pack2(bb0, bb1);

    for (int n0 = warp * 4; n0 < N; n0 += nw * 4) {
        float sr0[4], sr1[4], sr2[4], rcp[4], tv[4];
#pragma unroll
        for (int m = 0; m < 4; m++) {
            int n = n0 + m;
            if (n < N) {
                const float* so = g_S + (size_t)n * CH;
                sr0[m] = so[lane]; sr1[m] = so[32 + lane]; sr2[m] = so[64 + lane];
                int cnt = g_off[n + 1] - g_off[n];
                tv[m] = (cnt > 0) ? 1.f : 0.f;
                rcp[m] = (cnt > 0) ? 1.f / (float)cnt : 0.f;
            } else { sr0[m] = sr1[m] = sr2[m] = 0.f; tv[m] = 0.f; rcp[m] = 0.f; }
        }
        unsigned long long aA[4], aB[4];
#pragma unroll
        for (int m = 0; m < 4; m++) { aA[m] = 0ull; aB[m] = 0ull; }
#pragma unroll
        for (int cc = 0; cc < 32; cc++) {
            unsigned long long wA = *(const unsigned long long*)&W1pA[cc * 32 + lane];
            unsigned long long wB = *(const unsigned long long*)&W1pB[cc * 32 + lane];
#pragma unroll
            for (int m = 0; m < 4; m++) {
                unsigned long long vv = packdup(__shfl_sync(0xffffffffu, sr0[m], cc));
                fma2(aA[m], vv, wA); fma2(aB[m], vv, wB);
            }
        }
#pragma unroll
        for (int cc = 0; cc < 32; cc++) {
            unsigned long long wA = *(const unsigned long long*)&W1pA[(32 + cc) * 32 + lane];
            unsigned long long wB = *(const unsigned long long*)&W1pB[(32 + cc) * 32 + lane];
#pragma unroll
            for (int m = 0; m < 4; m++) {
                unsigned long long vv = packdup(__shfl_sync(0xffffffffu, sr1[m], cc));
                fma2(aA[m], vv, wA); fma2(aB[m], vv, wB);
            }
        }
#pragma unroll
        for (int cc = 0; cc < 24; cc++) {
            unsigned long long wA = *(const unsigned long long*)&W1pA[(64 + cc) * 32 + lane];
            unsigned long long wB = *(const unsigned long long*)&W1pB[(64 + cc) * 32 + lane];
#pragma unroll
            for (int m = 0; m < 4; m++) {
                unsigned long long vv = packdup(__shfl_sync(0xffffffffu, sr2[m], cc));
                fma2(aA[m], vv, wA); fma2(aB[m], vv, wB);
            }
        }
        float ag0[4], ag1[4], ag2[4], ag3[4];
#pragma unroll
        for (int m = 0; m < 4; m++) {
            float2 vA = *(float2*)&aA[m];
            float2 vB = *(float2*)&aB[m];
            ag0[m] = ((vA.x * rcp[m] + bo0 - mn0) * sc0 + bt0) * tv[m];
            ag1[m] = ((vA.y * rcp[m] + bo1 - mn1) * sc1 + bt1) * tv[m];
            ag2[m] = ((vB.x * rcp[m] + bo2 - mn2) * sc2 + bt2) * tv[m];
            ag3[m] = ((vB.y * rcp[m] + bo3 - mn3) * sc3 + bt3) * tv[m];
        }
        unsigned long long oP[4];
#pragma unroll
        for (int m = 0; m < 4; m++) oP[m] = bbP;
#pragma unroll
        for (int k = 0; k < 4; k++) {
            unsigned long long wp = *(const unsigned long long*)&W2p[k * 32 + lane];
#pragma unroll
            for (int m = 0; m < 4; m++) {
                int n = n0 + m;
                float xv = (n < N) ? x[(size_t)n * 4 + k] : 0.f;
                fma2(oP[m], packdup(xv), wp);
            }
        }
#pragma unroll
        for (int cc = 0; cc < 32; cc++) {
            unsigned long long wp = *(const unsigned long long*)&W2p[(4 + cc) * 32 + lane];
#pragma unroll
            for (int m = 0; m < 4; m++)
                fma2(oP[m], packdup(__shfl_sync(0xffffffffu, ag0[m], cc)), wp);
        }
#pragma unroll
        for (int cc = 0; cc < 32; cc++) {
            unsigned long long wp = *(const unsigned long long*)&W2p[(36 + cc) * 32 + lane];
#pragma unroll
            for (int m = 0; m < 4; m++)
                fma2(oP[m], packdup(__shfl_sync(0xffffffffu, ag1[m], cc)), wp);
        }
#pragma unroll
        for (int cc = 0; cc < 32; cc++) {
            unsigned long long wp = *(const unsigned long long*)&W2p[(68 + cc) * 32 + lane];
#pragma unroll
            for (int m = 0; m < 4; m++)
                fma2(oP[m], packdup(__shfl_sync(0xffffffffu, ag2[m], cc)), wp);
        }
#pragma unroll
        for (int cc = 0; cc < 32; cc++) {
            unsigned long long wp = *(const unsigned long long*)&W2p[(100 + cc) * 32 + lane];
#pragma unroll
            for (int m = 0; m < 4; m++)
                fma2(oP[m], packdup(__shfl_sync(0xffffffffu, ag3[m], cc)), wp);
        }
#pragma unroll
        for (int m = 0; m < 4; m++) {
            int n = n0 + m;
            if (n < N) {
                float2 o = *(float2*)&oP[m];
                out[(size_t)n * 64 + lane] = fmaxf(o.x, 0.f);
                out[(size_t)n * 64 + 32 + lane] = fmaxf(o.y, 0.f);
            }
        }
    }
}

// ---------------- launcher --------------------------------------------------
extern "C" void kernel_launch(void* const* d_in, const int* in_sizes, int n_in,
                              void* d_out, int out_size) {
    const float* x     = (const float*)d_in[0];
    const void*  ei    = d_in[1];
    const float* ea    = (const float*)d_in[2];
    const float* W1    = (const float*)d_in[3];
    const float* b1    = (const float*)d_in[4];
    const float* gamma = (const float*)d_in[5];
    const float* beta  = (const float*)d_in[6];
    const float* W2    = (const float*)d_in[7];
    const float* b2    = (const float*)d_in[8];
    float* out = (float*)d_out;
    int N = in_sizes[0] / 4;
    int E = in_sizes[2] / 84;
    int nb = (N + SCAN_CH - 1) / SCAN_CH;

    k_detect<<<1, 32>>>(ei);
    k_zero<<<512, 256>>>(N);
    k_convhist<<<512, 256>>>(ei, E);
    k_scanA<<<nb, 1024>>>(N);
    k_scanB<<<1, 32>>>(nb, N, E);
    k_scanC<<<(N + 255) / 256, 256>>>(N);
    k_perm<<<512, 256>>>(E);

    const int msmem = 2 * TILE_B;   // 52224 B
    cudaFuncSetAttribute(k_fused, cudaFuncAttributeMaxDynamicSharedMemorySize, msmem);
    k_fused<<<296, 256, msmem>>>(x, ea, E);

    k_bn<<<128, 96>>>(W1, b1, gamma, (float)E);
    const int osmem = (2 * 88 * 32 + 132 * 32) * 8;  // 78848 B
    cudaFuncSetAttribute(k_out, cudaFuncAttributeMaxDynamicSharedMemorySize, osmem);
    k_out<<<296, 256, osmem>>>(x, W1, b1, beta, W2, b2, out, N);
}

// round 13
// speedup vs baseline: 1.5569x; 1.0151x over previous
#include <cuda_runtime.h>
#include <cuda_bf16.h>
#include <cstdint>

#define MAXN 50000
#define MAXE 800000
#define CH 96          // padded feature channels (88 real: 4 x + 84 edge_attr)
#define OC 128
#define OUTC 64
#define EPSV 1e-5f
#define SCAN_CH 2048   // elements per scan CTA

// ---------------- device scratch (static globals: no allocs allowed) -------
__device__ int   g_is64;
__device__ int   g_row[MAXE];
__device__ int   g_col[MAXE];
__device__ int   g_cnt[MAXN];
__device__ int   g_off[MAXN + 1];
__device__ int   g_cur[MAXN];
__device__ int   g_perm[MAXE];
__device__ int   g_srow[MAXE];             // row id in perm order (sorted)
__device__ int   g_blk[64];
__device__ float g_S[(size_t)MAXN * CH];   // per-node summed features
__device__ float g_M[CH * CH];             // second-moment matrix sum f f^T
__device__ float g_sv[CH];                 // global feature sum s
__device__ float g_mean[OC];
__device__ float g_scale[OC];              // gamma * rsqrt(var+eps)

__device__ __forceinline__ uint32_t smem_u32(const void* p) {
    uint32_t a;
    asm("{ .reg .u64 t; cvta.to.shared.u64 t, %1; cvt.u32.u64 %0, t; }" : "=r"(a) : "l"(p));
    return a;
}
__device__ __forceinline__ void fma2(unsigned long long& d,
                                     unsigned long long a, unsigned long long b) {
    asm("fma.rn.f32x2 %0, %1, %2, %0;" : "+l"(d) : "l"(a), "l"(b));
}
__device__ __forceinline__ unsigned long long packdup(float v) {
    unsigned long long r;
    asm("mov.b64 %0, {%1, %1};" : "=l"(r) : "f"(v));
    return r;
}
__device__ __forceinline__ unsigned long long pack2(float lo, float hi) {
    unsigned long long r;
    asm("mov.b64 %0, {%1, %2};" : "=l"(r) : "f"(lo), "f"(hi));
    return r;
}

// ---------------- dtype detection: int64 vs int32 edge_index ----------------
__global__ void k_detect(const void* ei) {
    const long long* p = (const long long*)ei;
    int bad = 0;
    for (int i = threadIdx.x; i < 64; i += 32) {
        long long v = p[i];
        if (v < 0 || v >= MAXN) bad = 1;
    }
    unsigned m = __ballot_sync(0xffffffffu, bad);
    if (threadIdx.x == 0) g_is64 = (m == 0) ? 1 : 0;
}

// ---------------- zero scratch (g_cnt, g_M, g_sv, g_S) ----------------------
__global__ void k_zero(int N) {
    int i = blockIdx.x * blockDim.x + threadIdx.x;
    int T = gridDim.x * blockDim.x;
    for (int j = i; j < N; j += T) g_cnt[j] = 0;
    for (int j = i; j < CH * CH; j += T) g_M[j] = 0.f;
    size_t tot = (size_t)N * CH;
    for (size_t j = i; j < tot; j += T) g_S[j] = 0.f;
    if (i < CH) g_sv[i] = 0.f;
}

// ---------------- convert + histogram fused ---------------------------------
__global__ void k_convhist(const void* ei, int E) {
    int is64 = g_is64;
    int i = blockIdx.x * blockDim.x + threadIdx.x;
    int T = gridDim.x * blockDim.x;
    if (is64) {
        const long long* p = (const long long*)ei;
        for (int e = i; e < E; e += T) {
            int r = (int)p[e];
            g_row[e] = r; g_col[e] = (int)p[E + e];
            atomicAdd(&g_cnt[r], 1);
        }
    } else {
        const int* p = (const int*)ei;
        for (int e = i; e < E; e += T) {
            int r = p[e];
            g_row[e] = r; g_col[e] = p[E + e];
            atomicAdd(&g_cnt[r], 1);
        }
    }
}

// ---------------- multi-CTA exclusive scan ----------------------------------
__global__ void k_scanA(int N) {
    __shared__ int sc[1024];
    int b = blockIdx.x, t = threadIdx.x;
    int i0 = b * SCAN_CH + t * 2;
    int c0 = (i0 < N) ? g_cnt[i0] : 0;
    int c1 = (i0 + 1 < N) ? g_cnt[i0 + 1] : 0;
    int s = c0 + c1;
    sc[t] = s;
    __syncthreads();
#pragma unroll
    for (int d = 1; d < 1024; d <<= 1) {
        int v = (t >= d) ? sc[t - d] : 0;
        __syncthreads();
        sc[t] += v;
        __syncthreads();
    }
    int excl = sc[t] - s;
    if (i0 < N) g_off[i0] = excl;
    if (i0 + 1 < N) g_off[i0 + 1] = excl + c0;
    if (t == 1023) g_blk[b] = sc[1023];
}

// scanC with the 25-entry block-sum scan done locally (scanB folded in)
__global__ void k_scanC(int N, int nb, int E) {
    __shared__ int pref[32];
    int t = threadIdx.x;
    if (t < 32) {
        int v = (t < nb) ? g_blk[t] : 0;
        int incl = v;
#pragma unroll
        for (int d = 1; d < 32; d <<= 1) {
            int u = __shfl_up_sync(0xffffffffu, incl, d);
            if (t >= d) incl += u;
        }
        pref[t] = incl - v;   // exclusive
    }
    __syncthreads();
    int i = blockIdx.x * blockDim.x + t;
    if (i < N) {
        int v = g_off[i] + pref[i >> 11];
        g_off[i] = v;
        g_cur[i] = v;
    }
    if (i == 0) g_off[N] = E;
}

__global__ void k_perm(int E) {
    int i = blockIdx.x * blockDim.x + threadIdx.x;
    int T = gridDim.x * blockDim.x;
    for (int e = i; e < E; e += T) {
        int r = g_row[e];
        int p = atomicAdd(&g_cur[r], 1);
        g_perm[p] = e;
        g_srow[p] = r;
    }
}

// ---------------- FUSED: M = sum f f^T (HMMA) + per-node S (seg-reduce) ----
// Software-pipelined: chunk c's gather LDGs issue BEFORE chunk c-1's MMA phase,
// so the HMMA work executes under the DRAM-latency shadow.
#define KB 128
#define ROWB 272
#define TILE_B (CH * ROWB)   // 26112

__device__ __forceinline__ void ldm_x4(uint32_t* r, uint32_t a) {
    asm volatile("ldmatrix.sync.aligned.m8n8.x4.shared.b16 {%0,%1,%2,%3}, [%4];"
                 : "=r"(r[0]), "=r"(r[1]), "=r"(r[2]), "=r"(r[3]) : "r"(a));
}
__device__ __forceinline__ void ldm_x2(uint32_t* r, uint32_t a) {
    asm volatile("ldmatrix.sync.aligned.m8n8.x2.shared.b16 {%0,%1}, [%2];"
                 : "=r"(r[0]), "=r"(r[1]) : "r"(a));
}
__device__ __forceinline__ void mma_bf16(float* c, const uint32_t* a, const uint32_t* b) {
    asm volatile("mma.sync.aligned.m16n8k16.row.col.f32.bf16.bf16.f32 "
                 "{%0,%1,%2,%3}, {%4,%5,%6,%7}, {%8,%9}, {%0,%1,%2,%3};"
                 : "+f"(c[0]), "+f"(c[1]), "+f"(c[2]), "+f"(c[3])
                 : "r"(a[0]), "r"(a[1]), "r"(a[2]), "r"(a[3]), "r"(b[0]), "r"(b[1]));
}

__device__ __forceinline__ void fused_load8(const float* __restrict__ x,
                                            const float* __restrict__ ea, int E,
                                            long long base0, int lane,
                                            float* v0, float* v1, float* v2, int* rw) {
#pragma unroll
    for (int u = 0; u < 8; u++) {
        long long idx = base0 + u;
        int ok = idx < E;
        long long ide = ok ? idx : (long long)(E - 1);
        int e = g_perm[ide];
        rw[u] = g_srow[ide];
        const float* fe = ea + (size_t)e * 84;
        float p, q, r;
        if (lane < 4) p = x[g_col[e] * 4 + lane];
        else          p = __ldcs(fe + lane - 4);
        q = __ldcs(fe + 28 + lane);
        r = (lane < 24) ? __ldcs(fe + 60 + lane) : 0.f;
        float m = ok ? 1.f : 0.f;
        v0[u] = m * p; v1[u] = m * q; v2[u] = m * r;
    }
}

__device__ __forceinline__ void mma_phase(const char* tp, int Rm, int Rn, int lane,
                                          float acc[3][3][4]) {
    uint32_t tb = smem_u32(tp);
#pragma unroll
    for (int ks = 0; ks < KB / 16; ks++) {
        uint32_t af[3][4], bf[3][2];
#pragma unroll
        for (int i = 0; i < 3; i++) {
            uint32_t addr = tb + (uint32_t)((Rm + i * 16 + (lane & 15)) * ROWB
                                            + ks * 32 + (lane >> 4) * 16);
            ldm_x4(af[i], addr);
        }
#pragma unroll
        for (int j = 0; j < 3; j++) {
            uint32_t addr = tb + (uint32_t)((Rn + j * 8 + (lane & 7)) * ROWB
                                            + ks * 32 + ((lane >> 3) & 1) * 16);
            ldm_x2(bf[j], addr);
        }
#pragma unroll
        for (int i = 0; i < 3; i++)
#pragma unroll
            for (int j = 0; j < 3; j++) mma_bf16(acc[i][j], af[i], bf[j]);
    }
}

__global__ void __launch_bounds__(256, 2)
k_fused(const float* __restrict__ x, const float* __restrict__ ea, int E) {
    extern __shared__ __align__(16) char dsm[];   // 2 * TILE_B
    int tid = threadIdx.x;
    int lane = tid & 31, w = tid >> 5;
    int warp_m = w >> 2, warp_n = w & 3;   // 2 x 4
    int Rm = warp_m * 48;                  // 3 x 16 rows
    int Rn = warp_n * 24;                  // 3 x 8 cols

    float acc[3][3][4];
#pragma unroll
    for (int i = 0; i < 3; i++)
#pragma unroll
        for (int j = 0; j < 3; j++)
#pragma unroll
            for (int q = 0; q < 4; q++) acc[i][j][q] = 0.f;

    float s0 = 0.f, s1 = 0.f, s2 = 0.f;
    float aS0 = 0.f, aS1 = 0.f, aS2 = 0.f;
    int curRow = -1;

    int nchunk = (E + KB - 1) / KB;
    int wbuf = 0, have = 0;
    for (int c = blockIdx.x; c < nchunk; c += gridDim.x) {
        long long base = (long long)c * KB;
        char* tp = dsm + wbuf * TILE_B;
        float v0[8], v1[8], v2[8];
        int rw[8];

        // ---- half 0: issue gather LDGs (scoreboard pending) ----------------
        fused_load8(x, ea, E, base + w * 16, lane, v0, v1, v2, rw);

        // ---- overlap: MMA phase of previous chunk (other buffer) -----------
        if (have) mma_phase(dsm + (wbuf ^ 1) * TILE_B, Rm, Rn, lane, acc);

        // ---- consume half 0: pack/store + seg-reduce ------------------------
        {
            int ee0 = w * 16;
#pragma unroll
            for (int u = 0; u < 8; u += 2) {
                s0 += v0[u] + v0[u + 1];
                s1 += v1[u] + v1[u + 1];
                s2 += v2[u] + v2[u + 1];
                __nv_bfloat162 b0 = __floats2bfloat162_rn(v0[u], v0[u + 1]);
                __nv_bfloat162 b1 = __floats2bfloat162_rn(v1[u], v1[u + 1]);
                __nv_bfloat162 b2 = __floats2bfloat162_rn(v2[u], v2[u + 1]);
                int eo = (ee0 + u) * 2;
                *(__nv_bfloat162*)(tp + lane * ROWB + eo) = b0;
                *(__nv_bfloat162*)(tp + (32 + lane) * ROWB + eo) = b1;
                *(__nv_bfloat162*)(tp + (64 + lane) * ROWB + eo) = b2;
            }
#pragma unroll
            for (int u = 0; u < 8; u++) {
                if (rw[u] != curRow) {
                    if (curRow >= 0) {
                        float* dst = g_S + (size_t)curRow * CH;
                        atomicAdd(&dst[lane], aS0);
                        atomicAdd(&dst[32 + lane], aS1);
                        if (lane < 24) atomicAdd(&dst[64 + lane], aS2);
                    }
                    curRow = rw[u];
                    aS0 = 0.f; aS1 = 0.f; aS2 = 0.f;
                }
                aS0 += v0[u]; aS1 += v1[u]; aS2 += v2[u];
            }
        }

        // ---- half 1 ----------------------------------------------------------
        fused_load8(x, ea, E, base + w * 16 + 8, lane, v0, v1, v2, rw);
        {
            int ee0 = w * 16 + 8;
#pragma unroll
            for (int u = 0; u < 8; u += 2) {
                s0 += v0[u] + v0[u + 1];
                s1 += v1[u] + v1[u + 1];
                s2 += v2[u] + v2[u + 1];
                __nv_bfloat162 b0 = __floats2bfloat162_rn(v0[u], v0[u + 1]);
                __nv_bfloat162 b1 = __floats2bfloat162_rn(v1[u], v1[u + 1]);
                __nv_bfloat162 b2 = __floats2bfloat162_rn(v2[u], v2[u + 1]);
                int eo = (ee0 + u) * 2;
                *(__nv_bfloat162*)(tp + lane * ROWB + eo) = b0;
                *(__nv_bfloat162*)(tp + (32 + lane) * ROWB + eo) = b1;
                *(__nv_bfloat162*)(tp + (64 + lane) * ROWB + eo) = b2;
            }
#pragma unroll
            for (int u = 0; u < 8; u++) {
                if (rw[u] != curRow) {
                    if (curRow >= 0) {
                        float* dst = g_S + (size_t)curRow * CH;
                        atomicAdd(&dst[lane], aS0);
                        atomicAdd(&dst[32 + lane], aS1);
                        if (lane < 24) atomicAdd(&dst[64 + lane], aS2);
                    }
                    curRow = rw[u];
                    aS0 = 0.f; aS1 = 0.f; aS2 = 0.f;
                }
                aS0 += v0[u]; aS1 += v1[u]; aS2 += v2[u];
            }
        }
        __syncthreads();   // stores of wbuf visible; prior mma on wbuf^1 complete
        have = 1;
        wbuf ^= 1;
    }
    // epilogue: MMA for the last stored chunk
    if (have) mma_phase(dsm + (wbuf ^ 1) * TILE_B, Rm, Rn, lane, acc);

    if (curRow >= 0) {
        float* dst = g_S + (size_t)curRow * CH;
        atomicAdd(&dst[lane], aS0);
        atomicAdd(&dst[32 + lane], aS1);
        if (lane < 24) atomicAdd(&dst[64 + lane], aS2);
    }
#pragma unroll
    for (int i = 0; i < 3; i++)
#pragma unroll
        for (int j = 0; j < 3; j++) {
            int row = Rm + i * 16 + (lane >> 2);
            int col = Rn + j * 8 + (lane & 3) * 2;
            atomicAdd(&g_M[row * CH + col], acc[i][j][0]);
            atomicAdd(&g_M[row * CH + col + 1], acc[i][j][1]);
            atomicAdd(&g_M[(row + 8) * CH + col], acc[i][j][2]);
            atomicAdd(&g_M[(row + 8) * CH + col + 1], acc[i][j][3]);
        }
    atomicAdd(&g_sv[lane], s0);
    atomicAdd(&g_sv[32 + lane], s1);
    if (lane < 24) atomicAdd(&g_sv[64 + lane], s2);
}

// ---------------- BN stats --------------------------------------------------
__global__ void k_bn(const float* __restrict__ W1, const float* __restrict__ b1,
                     const float* __restrict__ gamma, float fE) {
    int c = blockIdx.x;
    int t = threadIdx.x;  // 96 threads
    __shared__ float w[CH];
    __shared__ float rq[CH];
    __shared__ float rs[CH];
    w[t] = (t < 88) ? W1[t * OC + c] : 0.f;
    __syncthreads();
    float q = 0.f;
    if (t < 88) {
        const float* Mr = g_M + t * CH;
        for (int k = 0; k < 88; k++) q += Mr[k] * w[k];
        q *= w[t];
    }
    rq[t] = q;
    rs[t] = (t < 88) ? g_sv[t] * w[t] : 0.f;
    __syncthreads();
    if (t == 0) {
        float Q = 0.f, SW = 0.f;
        for (int i = 0; i < 88; i++) { Q += rq[i]; SW += rs[i]; }
        float b = b1[c];
        float mean = SW / fE + b;
        float ex2 = (Q + 2.f * b * SW) / fE + b * b;
        float var = ex2 - mean * mean;
        g_mean[c] = mean;
        g_scale[c] = gamma[c] * rsqrtf(var + EPSV);
    }
}

// ---------------- node output: f32x2 packed math, 4 nodes per warp ----------
__global__ void k_out(const float* __restrict__ x, const float* __restrict__ W1,
                      const float* __restrict__ b1, const float* __restrict__ beta,
                      const float* __restrict__ W2, const float* __restrict__ b2,
                      float* __restrict__ out, int N) {
    extern __shared__ float2 smp[];
    float2* W1pA = smp;                // 2816
    float2* W1pB = smp + 88 * 32;      // 2816
    float2* W2p  = smp + 2 * 88 * 32;  // 4224
    int tid = threadIdx.x;
    for (int i = tid; i < 88 * 32; i += blockDim.x) {
        int cc = i >> 5, l = i & 31;
        W1pA[i] = make_float2(W1[cc * OC + l], W1[cc * OC + 32 + l]);
        W1pB[i] = make_float2(W1[cc * OC + 64 + l], W1[cc * OC + 96 + l]);
    }
    for (int i = tid; i < 132 * 32; i += blockDim.x) {
        int cc = i >> 5, l = i & 31;
        W2p[i] = make_float2(W2[cc * OUTC + l], W2[cc * OUTC + 32 + l]);
    }
    __syncthreads();
    int lane = tid & 31;
    int warp = (blockIdx.x * blockDim.x + tid) >> 5;
    int nw = (gridDim.x * blockDim.x) >> 5;
    float mn0 = g_mean[lane], mn1 = g_mean[32 + lane], mn2 = g_mean[64 + lane], mn3 = g_mean[96 + lane];
    float sc0 = g_scale[lane], sc1 = g_scale[32 + lane], sc2 = g_scale[64 + lane], sc3 = g_scale[96 + lane];
    float bt0 = beta[lane], bt1 = beta[32 + lane], bt2 = beta[64 + lane], bt3 = beta[96 + lane];
    float bo0 = b1[lane], bo1 = b1[32 + lane], bo2 = b1[64 + lane], bo3 = b1[96 + lane];
    float bb0 = b2[lane], bb1 = b2[32 + lane];
    unsigned long long bbP = pack2(bb0, bb1);

    for (int n0 = warp * 4; n0 < N; n0 += nw * 4) {
        float sr0[4], sr1[4], sr2[4], rcp[4], tv[4];
#pragma unroll
        for (int m = 0; m < 4; m++) {
            int n = n0 + m;
            if (n < N) {
                const float* so = g_S + (size_t)n * CH;
                sr0[m] = so[lane]; sr1[m] = so[32 + lane]; sr2[m] = so[64 + lane];
                int cnt = g_off[n + 1] - g_off[n];
                tv[m] = (cnt > 0) ? 1.f : 0.f;
                rcp[m] = (cnt > 0) ? 1.f / (float)cnt : 0.f;
            } else { sr0[m] = sr1[m] = sr2[m] = 0.f; tv[m] = 0.f; rcp[m] = 0.f; }
        }
        unsigned long long aA[4], aB[4];
#pragma unroll
        for (int m = 0; m < 4; m++) { aA[m] = 0ull; aB[m] = 0ull; }
#pragma unroll
        for (int cc = 0; cc < 32; cc++) {
            unsigned long long wA = *(const unsigned long long*)&W1pA[cc * 32 + lane];
            unsigned long long wB = *(const unsigned long long*)&W1pB[cc * 32 + lane];
#pragma unroll
            for (int m = 0; m < 4; m++) {
                unsigned long long vv = packdup(__shfl_sync(0xffffffffu, sr0[m], cc));
                fma2(aA[m], vv, wA); fma2(aB[m], vv, wB);
            }
        }
#pragma unroll
        for (int cc = 0; cc < 32; cc++) {
            unsigned long long wA = *(const unsigned long long*)&W1pA[(32 + cc) * 32 + lane];
            unsigned long long wB = *(const unsigned long long*)&W1pB[(32 + cc) * 32 + lane];
#pragma unroll
            for (int m = 0; m < 4; m++) {
                unsigned long long vv = packdup(__shfl_sync(0xffffffffu, sr1[m], cc));
                fma2(aA[m], vv, wA); fma2(aB[m], vv, wB);
            }
        }
#pragma unroll
        for (int cc = 0; cc < 24; cc++) {
            unsigned long long wA = *(const unsigned long long*)&W1pA[(64 + cc) * 32 + lane];
            unsigned long long wB = *(const unsigned long long*)&W1pB[(64 + cc) * 32 + lane];
#pragma unroll
            for (int m = 0; m < 4; m++) {
                unsigned long long vv = packdup(__shfl_sync(0xffffffffu, sr2[m], cc));
                fma2(aA[m], vv, wA); fma2(aB[m], vv, wB);
            }
        }
        float ag0[4], ag1[4], ag2[4], ag3[4];
#pragma unroll
        for (int m = 0; m < 4; m++) {
            float2 vA = *(float2*)&aA[m];
            float2 vB = *(float2*)&aB[m];
            ag0[m] = ((vA.x * rcp[m] + bo0 - mn0) * sc0 + bt0) * tv[m];
            ag1[m] = ((vA.y * rcp[m] + bo1 - mn1) * sc1 + bt1) * tv[m];
            ag2[m] = ((vB.x * rcp[m] + bo2 - mn2) * sc2 + bt2) * tv[m];
            ag3[m] = ((vB.y * rcp[m] + bo3 - mn3) * sc3 + bt3) * tv[m];
        }
        unsigned long long oP[4];
#pragma unroll
        for (int m = 0; m < 4; m++) oP[m] = bbP;
#pragma unroll
        for (int k = 0; k < 4; k++) {
            unsigned long long wp = *(const unsigned long long*)&W2p[k * 32 + lane];
#pragma unroll
            for (int m = 0; m < 4; m++) {
                int n = n0 + m;
                float xv = (n < N) ? x[(size_t)n * 4 + k] : 0.f;
                fma2(oP[m], packdup(xv), wp);
            }
        }
#pragma unroll
        for (int cc = 0; cc < 32; cc++) {
            unsigned long long wp = *(const unsigned long long*)&W2p[(4 + cc) * 32 + lane];
#pragma unroll
            for (int m = 0; m < 4; m++)
                fma2(oP[m], packdup(__shfl_sync(0xffffffffu, ag0[m], cc)), wp);
        }
#pragma unroll
        for (int cc = 0; cc < 32; cc++) {
            unsigned long long wp = *(const unsigned long long*)&W2p[(36 + cc) * 32 + lane];
#pragma unroll
            for (int m = 0; m < 4; m++)
                fma2(oP[m], packdup(__shfl_sync(0xffffffffu, ag1[m], cc)), wp);
        }
#pragma unroll
        for (int cc = 0; cc < 32; cc++) {
            unsigned long long wp = *(const unsigned long long*)&W2p[(68 + cc) * 32 + lane];
#pragma unroll
            for (int m = 0; m < 4; m++)
                fma2(oP[m], packdup(__shfl_sync(0xffffffffu, ag2[m], cc)), wp);
        }
#pragma unroll
        for (int cc = 0; cc < 32; cc++) {
            unsigned long long wp = *(const unsigned long long*)&W2p[(100 + cc) * 32 + lane];
#pragma unroll
            for (int m = 0; m < 4; m++)
                fma2(oP[m], packdup(__shfl_sync(0xffffffffu, ag3[m], cc)), wp);
        }
#pragma unroll
        for (int m = 0; m < 4; m++) {
            int n = n0 + m;
            if (n < N) {
                float2 o = *(float2*)&oP[m];
                out[(size_t)n * 64 + lane] = fmaxf(o.x, 0.f);
                out[(size_t)n * 64 + 32 + lane] = fmaxf(o.y, 0.f);
            }
        }
    }
}

// ---------------- launcher --------------------------------------------------
extern "C" void kernel_launch(void* const* d_in, const int* in_sizes, int n_in,
                              void* d_out, int out_size) {
    const float* x     = (const float*)d_in[0];
    const void*  ei    = d_in[1];
    const float* ea    = (const float*)d_in[2];
    const float* W1    = (const float*)d_in[3];
    const float* b1    = (const float*)d_in[4];
    const float* gamma = (const float*)d_in[5];
    const float* beta  = (const float*)d_in[6];
    const float* W2    = (const float*)d_in[7];
    const float* b2    = (const float*)d_in[8];
    float* out = (float*)d_out;
    int N = in_sizes[0] / 4;
    int E = in_sizes[2] / 84;
    int nb = (N + SCAN_CH - 1) / SCAN_CH;

    k_detect<<<1, 32>>>(ei);
    k_zero<<<512, 256>>>(N);
    k_convhist<<<512, 256>>>(ei, E);
    k_scanA<<<nb, 1024>>>(N);
    k_scanC<<<(N + 255) / 256, 256>>>(N, nb, E);
    k_perm<<<512, 256>>>(E);

    const int msmem = 2 * TILE_B;   // 52224 B
    cudaFuncSetAttribute(k_fused, cudaFuncAttributeMaxDynamicSharedMemorySize, msmem);
    k_fused<<<296, 256, msmem>>>(x, ea, E);

    k_bn<<<128, 96>>>(W1, b1, gamma, (float)E);
    const int osmem = (2 * 88 * 32 + 132 * 32) * 8;  // 78848 B
    cudaFuncSetAttribute(k_out, cudaFuncAttributeMaxDynamicSharedMemorySize, osmem);
    k_out<<<296, 256, osmem>>>(x, W1, b1, beta, W2, b2, out, N);
}